// round 11
// baseline (speedup 1.0000x reference)
#include <cuda_runtime.h>
#include <math.h>

#define EPS      1e-5f
#define LSEQ     32
#define DM       128
#define CIN      96
#define COUT     12
#define DIN      256
#define DST      16
#define NH       8
#define CDIM     288          // DIN + 2*DST
#define EPROJ    552          // 2*DIN + 2*DST + NH
#define TST      36           // hs transposed stride (conflict-free k-pair loads)
#define NT       256
#define MAXB     1024

#define IP_NT    69           // in_proj n-tiles (552/8)
#define IP_KC    8            // in_proj k16-chunks (128/16)
#define OP_NT    16           // out_proj n-tiles (128/8)
#define OP_KC    16           // out_proj k16-chunks (256/16)

typedef unsigned long long u64;

// device scratch: bf16 hi/lo fragment-packed weights (one 32-bit word = bf16x2)
#define IPF_N (4 * IP_NT * IP_KC * 128)   // 282624 words
#define OPF_N (4 * OP_NT * OP_KC * 128)   // 131072 words
__device__ unsigned g_ipf[IPF_N];
__device__ unsigned g_opf[OPF_N];
__device__ float g_A[(size_t)MAXB * 2 * DM];

// shared memory layout (floats)
#define OFF_BUF   0                          // 3072
#define OFF_HST   (OFF_BUF + CIN*LSEQ)       // 128*36 = 4608
#define OFF_ZX    (OFF_HST + DM*TST)         // 32*552 = 17664
#define OFF_DT    (OFF_ZX + LSEQ*EPROJ)      // 256
#define OFF_DA    (OFF_DT + LSEQ*NH)         // 256
#define OFF_INV   (OFF_DA + LSEQ*NH)         // 32
#define OFF_INV2  (OFF_INV + LSEQ)           // 32
#define OFF_RED   (OFF_INV2 + LSEQ)          // 256
#define SMEM_FLOATS (OFF_RED + NT)           // 26176 floats = 104704 B

__device__ __forceinline__ float sigmoidf_(float v) {
    return 1.f / (1.f + __expf(-v));
}
__device__ __forceinline__ u64 pk2(float lo, float hi) {
    u64 r; asm("mov.b64 %0,{%1,%2};" : "=l"(r) : "f"(lo), "f"(hi)); return r;
}
__device__ __forceinline__ u64 dup2(float v) { return pk2(v, v); }
__device__ __forceinline__ void upk2(u64 a, float& lo, float& hi) {
    asm("mov.b64 {%0,%1},%2;" : "=f"(lo), "=f"(hi) : "l"(a));
}
__device__ __forceinline__ u64 fma2_(u64 a, u64 b, u64 c) {
    u64 d; asm("fma.rn.f32x2 %0,%1,%2,%3;" : "=l"(d) : "l"(a), "l"(b), "l"(c)); return d;
}
__device__ __forceinline__ u64 mul2_(u64 a, u64 b) {
    u64 d; asm("mul.rn.f32x2 %0,%1,%2;" : "=l"(d) : "l"(a), "l"(b)); return d;
}
__device__ __forceinline__ u64 add2_(u64 a, u64 b) {
    u64 d; asm("add.rn.f32x2 %0,%1,%2;" : "=l"(d) : "l"(a), "l"(b)); return d;
}

// split (v0, v1) -> packed bf16x2 hi (rz-trunc) and lo (rn of residual)
__device__ __forceinline__ void bsplit(float v0, float v1, unsigned& hi, unsigned& lo) {
    unsigned u0 = __float_as_uint(v0), u1 = __float_as_uint(v1);
    asm("prmt.b32 %0,%1,%2,0x7632;" : "=r"(hi) : "r"(u0), "r"(u1));
    float h0 = __uint_as_float(u0 & 0xffff0000u);
    float h1 = __uint_as_float(u1 & 0xffff0000u);
    asm("cvt.rn.bf16x2.f32 %0,%1,%2;" : "=r"(lo) : "f"(v1 - h1), "f"(v0 - h0));
}
__device__ __forceinline__ void mma_bf16(float* d, const unsigned* a,
                                         unsigned b0, unsigned b1) {
    asm volatile(
        "mma.sync.aligned.m16n8k16.row.col.f32.bf16.bf16.f32 "
        "{%0,%1,%2,%3},{%4,%5,%6,%7},{%8,%9},{%0,%1,%2,%3};"
        : "+f"(d[0]), "+f"(d[1]), "+f"(d[2]), "+f"(d[3])
        : "r"(a[0]), "r"(a[1]), "r"(a[2]), "r"(a[3]), "r"(b0), "r"(b1));
}

// ---- prep: fold norms, bf16 hi/lo split, B-fragment lane order --------------
__global__ void prep_weights(const float* __restrict__ ipw,
                             const float* __restrict__ bnw,
                             const float* __restrict__ opw,
                             const float* __restrict__ mnw) {
    int i = blockIdx.x * blockDim.x + threadIdx.x;
    if (i < IPF_N) {
        int blk = i / (IP_NT * IP_KC * 128);
        int r   = i - blk * (IP_NT * IP_KC * 128);
        int n   = r / (IP_KC * 128);
        int q   = r - n * (IP_KC * 128);
        int kc  = q >> 7;
        int rem = q & 127;
        int lane = rem >> 2, comp = rem & 3;
        int g = lane >> 2, c = lane & 3;
        int e  = n * 8 + g;
        int k0 = kc * 16 + 2 * c + ((comp & 1) ? 8 : 0);
        float v0 = ipw[((size_t)blk * EPROJ + e) * DM + k0]     * bnw[blk * DM + k0];
        float v1 = ipw[((size_t)blk * EPROJ + e) * DM + k0 + 1] * bnw[blk * DM + k0 + 1];
        unsigned hi, lo;
        bsplit(v0, v1, hi, lo);
        g_ipf[i] = (comp < 2) ? hi : lo;
    } else if (i < IPF_N + OPF_N) {
        int j   = i - IPF_N;
        int blk = j >> 15;
        int r   = j & 32767;
        int n   = r >> 11;
        int q   = r & 2047;
        int kc  = q >> 7;
        int rem = q & 127;
        int lane = rem >> 2, comp = rem & 3;
        int g = lane >> 2, c = lane & 3;
        int d  = n * 8 + g;
        int e0 = kc * 16 + 2 * c + ((comp & 1) ? 8 : 0);
        float v0 = opw[((size_t)blk * DM + d) * DIN + e0]     * mnw[blk * DIN + e0];
        float v1 = opw[((size_t)blk * DM + d) * DIN + e0 + 1] * mnw[blk * DIN + e0 + 1];
        unsigned hi, lo;
        bsplit(v0, v1, hi, lo);
        g_opf[j] = (comp < 2) ? hi : lo;
    }
}

// ---- finalize ----------------------------------------------------------------
__global__ void finalize_kernel(const float* __restrict__ fow,
                                const float* __restrict__ fob,
                                const float* __restrict__ olw,
                                const float* __restrict__ olb,
                                float* __restrict__ out, int B) {
    int idx = blockIdx.x * blockDim.x + threadIdx.x;
    if (idx >= B * COUT) return;
    int b = idx / COUT, o = idx - b * COUT;
    float Swl = 0.f;
#pragma unroll
    for (int t = 0; t < LSEQ; t++) Swl += olw[t];
    const float* A0 = g_A + (size_t)b * 2 * DM;
    float acc = 0.f;
#pragma unroll 4
    for (int d = 0; d < DM; d++) acc = fmaf(fow[o * DM + d], A0[d] + A0[DM + d], acc);
    out[idx] = acc + fob[o] * Swl + olb[0];
}

// ---- main: one CTA per (batch, direction) -------------------------------------
__global__ void __launch_bounds__(NT, 2) mamba_actor_kernel(
    const float* __restrict__ x,        // (B, 96)
    const float* __restrict__ buffer,   // (B, 96, 32)
    const float* __restrict__ fiw,      // (128, 96)
    const float* __restrict__ fib,      // (128,)
    const float* __restrict__ cw,       // (4, 288, 4)
    const float* __restrict__ cb,       // (4, 288)
    const float* __restrict__ dtb,      // (4, 8)
    const float* __restrict__ alog,     // (4, 8)
    const float* __restrict__ Dp,       // (4, 8)
    const float* __restrict__ nfw,      // (2, 128)
    const float* __restrict__ olw,      // (1, 32)
    float* __restrict__ out)
{
    extern __shared__ float sm[];
    float* s_buf  = sm + OFF_BUF;
    float* s_hsT  = sm + OFF_HST;   // [k][t], stride TST
    float* s_zx   = sm + OFF_ZX;    // [t][e], stride EPROJ
    float* s_dt   = sm + OFF_DT;
    float* s_dA   = sm + OFF_DA;
    float* s_inv  = sm + OFF_INV;
    float* s_inv2 = sm + OFF_INV2;
    float* s_red  = sm + OFF_RED;

    const int B    = gridDim.x >> 1;
    const int b    = blockIdx.x >> 1;
    const int dir  = blockIdx.x & 1;
    const int tid  = threadIdx.x;
    const int lane = tid & 31;
    const int warp = tid >> 5;
    const int kb   = lane & 3;      // c: thread-in-group
    const int tb   = lane >> 2;     // g: group id (row)

    // ---- Stage 0: shifted buffer -> smem (dir-flipped) + buf output ----------
    {
        const float* bsrc = buffer + (size_t)b * CIN * LSEQ;
        const float* xsrc = x + (size_t)b * CIN;
        float* bdst = out + (size_t)B * COUT + (size_t)b * CIN * LSEQ;
        for (int idx = tid; idx < CIN * LSEQ; idx += NT) {
            int c = idx >> 5, l = idx & 31;
            float v = (l < LSEQ - 1) ? bsrc[c * LSEQ + l + 1] : xsrc[c];
            int ls = dir ? (LSEQ - 1 - l) : l;
            s_buf[c * LSEQ + ls] = v;
            if (dir == 0) bdst[idx] = v;
        }
    }
    __syncthreads();

    // ---- fc_in (f32x2): thread = (d, t-half) ---------------------------------
    {
        int d   = tid >> 1;
        int tph = tid & 1;
        u64 acc2[8];
        u64 bias = dup2(fib[d]);
#pragma unroll
        for (int p = 0; p < 8; p++) acc2[p] = bias;
        const float4* wrow = reinterpret_cast<const float4*>(fiw + d * CIN);
#pragma unroll 2
        for (int cc = 0; cc < CIN / 4; cc++) {
            float4 w4 = wrow[cc];
            u64 w0 = dup2(w4.x), w1 = dup2(w4.y), w2 = dup2(w4.z), w3 = dup2(w4.w);
            const u64* b0 = reinterpret_cast<const u64*>(s_buf + (cc * 4 + 0) * LSEQ + tph * 16);
            const u64* b1 = reinterpret_cast<const u64*>(s_buf + (cc * 4 + 1) * LSEQ + tph * 16);
            const u64* b2 = reinterpret_cast<const u64*>(s_buf + (cc * 4 + 2) * LSEQ + tph * 16);
            const u64* b3 = reinterpret_cast<const u64*>(s_buf + (cc * 4 + 3) * LSEQ + tph * 16);
#pragma unroll
            for (int p = 0; p < 8; p++) {
                acc2[p] = fma2_(b0[p], w0, acc2[p]);
                acc2[p] = fma2_(b1[p], w1, acc2[p]);
                acc2[p] = fma2_(b2[p], w2, acc2[p]);
                acc2[p] = fma2_(b3[p], w3, acc2[p]);
            }
        }
        u64* hdst = reinterpret_cast<u64*>(s_hsT + d * TST + tph * 16);
#pragma unroll
        for (int p = 0; p < 8; p++) hdst[p] = acc2[p];
    }
    __syncthreads();

    for (int l = 0; l < 2; l++) {
        const int blk = dir * 2 + l;

        // ---- block rmsnorm over d (transposed layout) ------------------------
        {
            float s = 0.f;
#pragma unroll
            for (int q = 0; q < 16; q++) {
                float v = s_hsT[(warp * 16 + q) * TST + lane];
                s += v * v;
            }
            s_red[warp * 32 + lane] = s;
        }
        __syncthreads();
        if (tid < 32) {
            float s = 0.f;
#pragma unroll
            for (int w = 0; w < 8; w++) s += s_red[w * 32 + tid];
            s_inv[tid] = rsqrtf(s * (1.f / DM) + EPS);
        }
        __syncthreads();

        // ---- in_proj via bf16 tensor cores (3-pass): D[t][e] = hs . W1 --------
        {
            const unsigned* Wf = g_ipf + (size_t)blk * (IP_NT * IP_KC * 128);
            float dacc[9][2][4];
#pragma unroll
            for (int j = 0; j < 9; j++)
#pragma unroll
                for (int m = 0; m < 2; m++)
#pragma unroll
                    for (int q = 0; q < 4; q++) dacc[j][m][q] = 0.f;

#pragma unroll 2
            for (int kc = 0; kc < IP_KC; kc++) {
                unsigned ah[2][4], al[2][4];
#pragma unroll
                for (int m = 0; m < 2; m++) {
#pragma unroll
                    for (int r = 0; r < 4; r++) {
                        int tt = m * 16 + tb + (r & 1) * 8;
                        int k  = kc * 16 + 2 * kb + (r >> 1) * 8;
                        float v0 = s_hsT[k * TST + tt];
                        float v1 = s_hsT[(k + 1) * TST + tt];
                        bsplit(v0, v1, ah[m][r], al[m][r]);
                    }
                }
#pragma unroll
                for (int j = 0; j < 9; j++) {
                    int n = warp + j * 8;
                    if (n < IP_NT) {
                        uint4 bf = *reinterpret_cast<const uint4*>(
                            Wf + ((size_t)(n * IP_KC + kc)) * 128 + lane * 4);
#pragma unroll
                        for (int m = 0; m < 2; m++) {
                            mma_bf16(dacc[j][m], ah[m], bf.x, bf.y);
                            mma_bf16(dacc[j][m], ah[m], bf.z, bf.w);
                            mma_bf16(dacc[j][m], al[m], bf.x, bf.y);
                        }
                    }
                }
            }
            // epilogue: scale rows by inv[t], store to zx
#pragma unroll
            for (int j = 0; j < 9; j++) {
                int n = warp + j * 8;
                if (n < IP_NT) {
#pragma unroll
                    for (int m = 0; m < 2; m++) {
                        int t0 = m * 16 + tb;
                        float i0 = s_inv[t0], i1 = s_inv[t0 + 8];
                        int e0 = n * 8 + 2 * kb;
                        float2 v0 = make_float2(dacc[j][m][0] * i0, dacc[j][m][1] * i0);
                        float2 v1 = make_float2(dacc[j][m][2] * i1, dacc[j][m][3] * i1);
                        *reinterpret_cast<float2*>(s_zx + t0 * EPROJ + e0) = v0;
                        *reinterpret_cast<float2*>(s_zx + (t0 + 8) * EPROJ + e0) = v1;
                    }
                }
            }
        }
        __syncthreads();

        // ---- dt/dA (256 threads == 32 t * 8 heads) + conv boundary pre-reads --
        {
            int t = tid >> 3, h = tid & 7;
            float v  = s_zx[t * EPROJ + DIN + CDIM + h] + dtb[blk * NH + h];
            float sp = (v > 20.f) ? v : log1pf(__expf(v));
            s_dt[t * NH + h] = sp;
            s_dA[t * NH + h] = __expf(-__expf(alog[blk * NH + h]) * sp);
        }
        float pre[2][3];
        {
            int nb = 0;
            for (int u = tid; u < 2 * CDIM; u += NT) {
                if (u >= CDIM) {
                    float* col = s_zx + DIN + (u - CDIM);
                    pre[nb][0] = col[13 * EPROJ];
                    pre[nb][1] = col[14 * EPROJ];
                    pre[nb][2] = col[15 * EPROJ];
                    nb++;
                }
            }
        }
        __syncthreads();

        // ---- causal depthwise conv (k=4) + silu, (c, t-half) units ------------
        {
            int nb = 0;
            for (int u = tid; u < 2 * CDIM; u += NT) {
                int half = (u >= CDIM);
                int c = half ? u - CDIM : u;
                float4 w4 = *reinterpret_cast<const float4*>(cw + ((size_t)blk * CDIM + c) * 4);
                float bb  = cb[blk * CDIM + c];
                float x0, x1, x2;
                if (half) { x0 = pre[nb][0]; x1 = pre[nb][1]; x2 = pre[nb][2]; nb++; }
                else      { x0 = 0.f; x1 = 0.f; x2 = 0.f; }
                float* col = s_zx + DIN + c + (half ? 16 * EPROJ : 0);
#pragma unroll
                for (int tt = 0; tt < 16; tt++) {
                    float xc = col[tt * EPROJ];
                    float o  = fmaf(w4.x, x0, fmaf(w4.y, x1, fmaf(w4.z, x2, fmaf(w4.w, xc, bb))));
                    col[tt * EPROJ] = o * sigmoidf_(o);
                    x0 = x1; x1 = x2; x2 = xc;
                }
            }
        }
        __syncthreads();

        // ---- SSM scan (+ fused gate): thread = (head, p) ----------------------
        // restructured: all state updates, then dual-chain y reduction
        {
            int h = tid >> 5;
            u64 st2[NH];
#pragma unroll
            for (int n = 0; n < 8; n++) st2[n] = 0ull;
            float dskip = Dp[blk * NH + h];
            for (int t = 0; t < LSEQ; t++) {
                float* row = s_zx + t * EPROJ;
                float xv  = row[DIN + tid];
                float z   = row[tid];
                float dAv = s_dA[t * NH + h];
                float dtv = s_dt[t * NH + h];
                u64 dA2  = dup2(dAv);
                u64 dtx2 = dup2(dtv * xv);
                ulonglong2 b20 = reinterpret_cast<const ulonglong2*>(row + 2 * DIN)[0];
                ulonglong2 b21 = reinterpret_cast<const ulonglong2*>(row + 2 * DIN)[1];
                ulonglong2 c20 = reinterpret_cast<const ulonglong2*>(row + 2 * DIN + DST)[0];
                ulonglong2 c21 = reinterpret_cast<const ulonglong2*>(row + 2 * DIN + DST)[1];
                ulonglong2 b22 = reinterpret_cast<const ulonglong2*>(row + 2 * DIN)[2];
                ulonglong2 b23 = reinterpret_cast<const ulonglong2*>(row + 2 * DIN)[3];
                ulonglong2 c22 = reinterpret_cast<const ulonglong2*>(row + 2 * DIN + DST)[2];
                ulonglong2 c23 = reinterpret_cast<const ulonglong2*>(row + 2 * DIN + DST)[3];
                // state updates (8 independent chains)
                st2[0] = fma2_(st2[0], dA2, mul2_(dtx2, b20.x));
                st2[1] = fma2_(st2[1], dA2, mul2_(dtx2, b20.y));
                st2[2] = fma2_(st2[2], dA2, mul2_(dtx2, b21.x));
                st2[3] = fma2_(st2[3], dA2, mul2_(dtx2, b21.y));
                st2[4] = fma2_(st2[4], dA2, mul2_(dtx2, b22.x));
                st2[5] = fma2_(st2[5], dA2, mul2_(dtx2, b22.y));
                st2[6] = fma2_(st2[6], dA2, mul2_(dtx2, b23.x));
                st2[7] = fma2_(st2[7], dA2, mul2_(dtx2, b23.y));
                // dual-chain y reduction
                u64 y2a = mul2_(st2[0], c20.x);
                u64 y2b = mul2_(st2[1], c20.y);
                y2a = fma2_(st2[2], c21.x, y2a);
                y2b = fma2_(st2[3], c21.y, y2b);
                y2a = fma2_(st2[4], c22.x, y2a);
                y2b = fma2_(st2[5], c22.y, y2b);
                y2a = fma2_(st2[6], c23.x, y2a);
                y2b = fma2_(st2[7], c23.y, y2b);
                u64 y2 = add2_(y2a, y2b);
                float ylo, yhi;
                upk2(y2, ylo, yhi);
                float yv = fmaf(dskip, xv, ylo + yhi);
                row[DIN + tid] = yv * z * sigmoidf_(z);   // fused gate
            }
        }
        __syncthreads();

        // ---- mixer rmsnorm factor over gated g --------------------------------
        {
            int t = tid >> 3, part = tid & 7;
            const float4* gp = reinterpret_cast<const float4*>(s_zx + t * EPROJ + DIN + part * 32);
            float s = 0.f;
#pragma unroll
            for (int q = 0; q < 8; q++) {
                float4 v = gp[q];
                s += v.x * v.x + v.y * v.y + v.z * v.z + v.w * v.w;
            }
            s += __shfl_xor_sync(0xffffffffu, s, 1);
            s += __shfl_xor_sync(0xffffffffu, s, 2);
            s += __shfl_xor_sync(0xffffffffu, s, 4);
            if (part == 0) s_inv2[t] = rsqrtf(s * (1.f / DIN) + EPS);
        }
        __syncthreads();

        // ---- out_proj via bf16 tensor cores (3-pass) + residual ---------------
        {
            const unsigned* Wf = g_opf + (size_t)blk * (OP_NT * OP_KC * 128);
            float dacc[2][2][4];
#pragma unroll
            for (int j = 0; j < 2; j++)
#pragma unroll
                for (int m = 0; m < 2; m++)
#pragma unroll
                    for (int q = 0; q < 4; q++) dacc[j][m][q] = 0.f;

#pragma unroll 4
            for (int kc = 0; kc < OP_KC; kc++) {
                unsigned ah[2][4], al[2][4];
#pragma unroll
                for (int m = 0; m < 2; m++) {
#pragma unroll
                    for (int r = 0; r < 4; r++) {
                        int tt = m * 16 + tb + (r & 1) * 8;
                        int e  = DIN + kc * 16 + 2 * kb + (r >> 1) * 8;
                        float2 v = *reinterpret_cast<const float2*>(s_zx + tt * EPROJ + e);
                        bsplit(v.x, v.y, ah[m][r], al[m][r]);
                    }
                }
#pragma unroll
                for (int j = 0; j < 2; j++) {
                    int n = warp + j * 8;
                    uint4 bf = *reinterpret_cast<const uint4*>(
                        Wf + ((size_t)(n * OP_KC + kc)) * 128 + lane * 4);
#pragma unroll
                    for (int m = 0; m < 2; m++) {
                        mma_bf16(dacc[j][m], ah[m], bf.x, bf.y);
                        mma_bf16(dacc[j][m], ah[m], bf.z, bf.w);
                        mma_bf16(dacc[j][m], al[m], bf.x, bf.y);
                    }
                }
            }
            // epilogue: hsT[d][t] += inv2[t] * D[t][d]
#pragma unroll
            for (int j = 0; j < 2; j++) {
                int n = warp + j * 8;
#pragma unroll
                for (int m = 0; m < 2; m++) {
                    int t0 = m * 16 + tb;
                    float i0 = s_inv2[t0], i1 = s_inv2[t0 + 8];
                    int d0 = n * 8 + 2 * kb;
                    s_hsT[d0 * TST + t0]           += dacc[j][m][0] * i0;
                    s_hsT[(d0 + 1) * TST + t0]     += dacc[j][m][1] * i0;
                    s_hsT[d0 * TST + t0 + 8]       += dacc[j][m][2] * i1;
                    s_hsT[(d0 + 1) * TST + t0 + 8] += dacc[j][m][3] * i1;
                }
            }
        }
        __syncthreads();
    } // layer

    // ---- final rmsnorm(norm_f) over d ------------------------------------------
    {
        float s = 0.f;
#pragma unroll
        for (int q = 0; q < 16; q++) {
            float v = s_hsT[(warp * 16 + q) * TST + lane];
            s += v * v;
        }
        s_red[warp * 32 + lane] = s;
    }
    __syncthreads();
    if (tid < 32) {
        float s = 0.f;
#pragma unroll
        for (int w = 0; w < 8; w++) s += s_red[w * 32 + tid];
        s_inv[tid] = rsqrtf(s * (1.f / DM) + EPS);
    }
    __syncthreads();

    // ---- L-weighted accumulate -> g_A ------------------------------------------
    if (tid < DM) {
        const float* hrow = s_hsT + tid * TST;
        float s = 0.f;
#pragma unroll
        for (int t = 0; t < LSEQ; t++) {
            float wl = olw[dir ? (LSEQ - 1 - t) : t];
            s = fmaf(wl * s_inv[t], hrow[t], s);
        }
        g_A[((size_t)b * 2 + dir) * DM + tid] = s * nfw[dir * DM + tid];
    }
}

extern "C" void kernel_launch(void* const* d_in, const int* in_sizes, int n_in,
                              void* d_out, int out_size) {
    const float* x      = (const float*)d_in[0];
    const float* buffer = (const float*)d_in[1];
    const float* fiw    = (const float*)d_in[2];
    const float* fib    = (const float*)d_in[3];
    const float* bnw    = (const float*)d_in[4];
    const float* ipw    = (const float*)d_in[5];
    const float* cw     = (const float*)d_in[6];
    const float* cb     = (const float*)d_in[7];
    const float* dtb    = (const float*)d_in[8];
    const float* alog   = (const float*)d_in[9];
    const float* Dp     = (const float*)d_in[10];
    const float* mnw    = (const float*)d_in[11];
    const float* opw    = (const float*)d_in[12];
    const float* nfw    = (const float*)d_in[13];
    const float* fow    = (const float*)d_in[14];
    const float* fob    = (const float*)d_in[15];
    const float* olw    = (const float*)d_in[16];
    const float* olb    = (const float*)d_in[17];
    float* out = (float*)d_out;

    int B = in_sizes[0] / CIN;   // 1024
    size_t smem_bytes = (size_t)SMEM_FLOATS * sizeof(float);

    cudaFuncSetAttribute(mamba_actor_kernel,
                         cudaFuncAttributeMaxDynamicSharedMemorySize,
                         (int)smem_bytes);

    int prep_total = IPF_N + OPF_N;
    prep_weights<<<(prep_total + 255) / 256, 256>>>(ipw, bnw, opw, mnw);

    mamba_actor_kernel<<<2 * B, NT, smem_bytes>>>(
        x, buffer, fiw, fib, cw, cb, dtb, alog,
        Dp, nfw, olw, out);

    finalize_kernel<<<(B * COUT + 255) / 256, 256>>>(fow, fob, olw, olb, out, B);
}

// round 12
// speedup vs baseline: 1.0430x; 1.0430x over previous
#include <cuda_runtime.h>
#include <math.h>

#define EPS      1e-5f
#define LSEQ     32
#define DM       128
#define CIN      96
#define COUT     12
#define DIN      256
#define DST      16
#define NH       8
#define CDIM     288          // DIN + 2*DST
#define EPROJ    552          // 2*DIN + 2*DST + NH
#define TST      36           // hs transposed stride (conflict-free k-pair loads)
#define NT       256
#define MAXB     1024

#define IP_NT    69           // in_proj n-tiles (552/8)
#define IP_KC    8            // in_proj k16-chunks (128/16)
#define OP_NT    16           // out_proj n-tiles (128/8)
#define OP_KC    16           // out_proj k16-chunks (256/16)

typedef unsigned long long u64;

// device scratch: bf16 hi/lo fragment-packed weights (one 32-bit word = bf16x2)
#define IPF_N (4 * IP_NT * IP_KC * 128)   // 282624 words
#define OPF_N (4 * OP_NT * OP_KC * 128)   // 131072 words
__device__ unsigned g_ipf[IPF_N];
__device__ unsigned g_opf[OPF_N];
__device__ float g_A[(size_t)MAXB * 2 * DM];

// shared memory layout (floats)
// OFF_APK: 4096 words, in_proj packed A fragments (hi:0..2047, lo:2048..4095).
//          Overlays s_buf (stage0/fc_in only, dead afterwards).
#define OFF_APK   0
#define OFF_HST   4096                       // 128*36 = 4608
#define OFF_ZX    (OFF_HST + DM*TST)         // 32*552 = 17664
#define OFF_DT    (OFF_ZX + LSEQ*EPROJ)      // 256
#define OFF_DA    (OFF_DT + LSEQ*NH)         // 256
#define OFF_INV   (OFF_DA + LSEQ*NH)         // 32
#define OFF_INV2  (OFF_INV + LSEQ)           // 32
#define OFF_RED   (OFF_INV2 + LSEQ)          // 256
#define SMEM_FLOATS (OFF_RED + NT)           // 27200 floats = 108800 B

// out_proj packed A lives in dead z-columns of s_zx: word w -> row w>>8, col w&255
#define ZIDX(w) ((((w) >> 8) * EPROJ) + ((w) & 255))

__device__ __forceinline__ float sigmoidf_(float v) {
    return 1.f / (1.f + __expf(-v));
}
__device__ __forceinline__ u64 pk2(float lo, float hi) {
    u64 r; asm("mov.b64 %0,{%1,%2};" : "=l"(r) : "f"(lo), "f"(hi)); return r;
}
__device__ __forceinline__ u64 dup2(float v) { return pk2(v, v); }
__device__ __forceinline__ void upk2(u64 a, float& lo, float& hi) {
    asm("mov.b64 {%0,%1},%2;" : "=f"(lo), "=f"(hi) : "l"(a));
}
__device__ __forceinline__ u64 fma2_(u64 a, u64 b, u64 c) {
    u64 d; asm("fma.rn.f32x2 %0,%1,%2,%3;" : "=l"(d) : "l"(a), "l"(b), "l"(c)); return d;
}
__device__ __forceinline__ u64 mul2_(u64 a, u64 b) {
    u64 d; asm("mul.rn.f32x2 %0,%1,%2;" : "=l"(d) : "l"(a), "l"(b)); return d;
}

// split (v0, v1) -> packed bf16x2 hi (rz-trunc) and lo (rn of residual)
__device__ __forceinline__ void bsplit(float v0, float v1, unsigned& hi, unsigned& lo) {
    unsigned u0 = __float_as_uint(v0), u1 = __float_as_uint(v1);
    asm("prmt.b32 %0,%1,%2,0x7632;" : "=r"(hi) : "r"(u0), "r"(u1));
    float h0 = __uint_as_float(u0 & 0xffff0000u);
    float h1 = __uint_as_float(u1 & 0xffff0000u);
    asm("cvt.rn.bf16x2.f32 %0,%1,%2;" : "=r"(lo) : "f"(v1 - h1), "f"(v0 - h0));
}
__device__ __forceinline__ void mma_bf16(float* d, const unsigned* a,
                                         unsigned b0, unsigned b1) {
    asm volatile(
        "mma.sync.aligned.m16n8k16.row.col.f32.bf16.bf16.f32 "
        "{%0,%1,%2,%3},{%4,%5,%6,%7},{%8,%9},{%0,%1,%2,%3};"
        : "+f"(d[0]), "+f"(d[1]), "+f"(d[2]), "+f"(d[3])
        : "r"(a[0]), "r"(a[1]), "r"(a[2]), "r"(a[3]), "r"(b0), "r"(b1));
}

// ---- prep: fold norms, bf16 hi/lo split, B-fragment lane order --------------
__global__ void prep_weights(const float* __restrict__ ipw,
                             const float* __restrict__ bnw,
                             const float* __restrict__ opw,
                             const float* __restrict__ mnw) {
    int i = blockIdx.x * blockDim.x + threadIdx.x;
    if (i < IPF_N) {
        int blk = i / (IP_NT * IP_KC * 128);
        int r   = i - blk * (IP_NT * IP_KC * 128);
        int n   = r / (IP_KC * 128);
        int q   = r - n * (IP_KC * 128);
        int kc  = q >> 7;
        int rem = q & 127;
        int lane = rem >> 2, comp = rem & 3;
        int g = lane >> 2, c = lane & 3;
        int e  = n * 8 + g;
        int k0 = kc * 16 + 2 * c + ((comp & 1) ? 8 : 0);
        float v0 = ipw[((size_t)blk * EPROJ + e) * DM + k0]     * bnw[blk * DM + k0];
        float v1 = ipw[((size_t)blk * EPROJ + e) * DM + k0 + 1] * bnw[blk * DM + k0 + 1];
        unsigned hi, lo;
        bsplit(v0, v1, hi, lo);
        g_ipf[i] = (comp < 2) ? hi : lo;
    } else if (i < IPF_N + OPF_N) {
        int j   = i - IPF_N;
        int blk = j >> 15;
        int r   = j & 32767;
        int n   = r >> 11;
        int q   = r & 2047;
        int kc  = q >> 7;
        int rem = q & 127;
        int lane = rem >> 2, comp = rem & 3;
        int g = lane >> 2, c = lane & 3;
        int d  = n * 8 + g;
        int e0 = kc * 16 + 2 * c + ((comp & 1) ? 8 : 0);
        float v0 = opw[((size_t)blk * DM + d) * DIN + e0]     * mnw[blk * DIN + e0];
        float v1 = opw[((size_t)blk * DM + d) * DIN + e0 + 1] * mnw[blk * DIN + e0 + 1];
        unsigned hi, lo;
        bsplit(v0, v1, hi, lo);
        g_opf[j] = (comp < 2) ? hi : lo;
    }
}

// ---- finalize ----------------------------------------------------------------
__global__ void finalize_kernel(const float* __restrict__ fow,
                                const float* __restrict__ fob,
                                const float* __restrict__ olw,
                                const float* __restrict__ olb,
                                float* __restrict__ out, int B) {
    int idx = blockIdx.x * blockDim.x + threadIdx.x;
    if (idx >= B * COUT) return;
    int b = idx / COUT, o = idx - b * COUT;
    float Swl = 0.f;
#pragma unroll
    for (int t = 0; t < LSEQ; t++) Swl += olw[t];
    const float* A0 = g_A + (size_t)b * 2 * DM;
    float acc = 0.f;
#pragma unroll 4
    for (int d = 0; d < DM; d++) acc = fmaf(fow[o * DM + d], A0[d] + A0[DM + d], acc);
    out[idx] = acc + fob[o] * Swl + olb[0];
}

// ---- main: one CTA per (batch, direction) -------------------------------------
__global__ void __launch_bounds__(NT, 2) mamba_actor_kernel(
    const float* __restrict__ x,        // (B, 96)
    const float* __restrict__ buffer,   // (B, 96, 32)
    const float* __restrict__ fiw,      // (128, 96)
    const float* __restrict__ fib,      // (128,)
    const float* __restrict__ cw,       // (4, 288, 4)
    const float* __restrict__ cb,       // (4, 288)
    const float* __restrict__ dtb,      // (4, 8)
    const float* __restrict__ alog,     // (4, 8)
    const float* __restrict__ Dp,       // (4, 8)
    const float* __restrict__ nfw,      // (2, 128)
    const float* __restrict__ olw,      // (1, 32)
    float* __restrict__ out)
{
    extern __shared__ float sm[];
    float*    s_buf  = sm + OFF_APK;   // stage0/fc_in only
    unsigned* s_apk  = reinterpret_cast<unsigned*>(sm + OFF_APK);
    float*    s_hsT  = sm + OFF_HST;   // [k][t], stride TST
    float*    s_zx   = sm + OFF_ZX;    // [t][e], stride EPROJ
    unsigned* s_zxw  = reinterpret_cast<unsigned*>(sm + OFF_ZX);
    float*    s_dt   = sm + OFF_DT;
    float*    s_dA   = sm + OFF_DA;
    float*    s_inv  = sm + OFF_INV;
    float*    s_inv2 = sm + OFF_INV2;
    float*    s_red  = sm + OFF_RED;

    const int B    = gridDim.x >> 1;
    const int b    = blockIdx.x >> 1;
    const int dir  = blockIdx.x & 1;
    const int tid  = threadIdx.x;
    const int lane = tid & 31;
    const int warp = tid >> 5;
    const int kb   = lane & 3;      // c: thread-in-group
    const int tb   = lane >> 2;     // g: group id (row)

    // ---- Stage 0: shifted buffer -> smem (dir-flipped) + buf output ----------
    {
        const float* bsrc = buffer + (size_t)b * CIN * LSEQ;
        const float* xsrc = x + (size_t)b * CIN;
        float* bdst = out + (size_t)B * COUT + (size_t)b * CIN * LSEQ;
        for (int idx = tid; idx < CIN * LSEQ; idx += NT) {
            int c = idx >> 5, l = idx & 31;
            float v = (l < LSEQ - 1) ? bsrc[c * LSEQ + l + 1] : xsrc[c];
            int ls = dir ? (LSEQ - 1 - l) : l;
            s_buf[c * LSEQ + ls] = v;
            if (dir == 0) bdst[idx] = v;
        }
    }
    __syncthreads();

    // ---- fc_in (f32x2): thread = (d, t-half) ---------------------------------
    {
        int d   = tid >> 1;
        int tph = tid & 1;
        u64 acc2[8];
        u64 bias = dup2(fib[d]);
#pragma unroll
        for (int p = 0; p < 8; p++) acc2[p] = bias;
        const float4* wrow = reinterpret_cast<const float4*>(fiw + d * CIN);
#pragma unroll 2
        for (int cc = 0; cc < CIN / 4; cc++) {
            float4 w4 = wrow[cc];
            u64 w0 = dup2(w4.x), w1 = dup2(w4.y), w2 = dup2(w4.z), w3 = dup2(w4.w);
            const u64* b0 = reinterpret_cast<const u64*>(s_buf + (cc * 4 + 0) * LSEQ + tph * 16);
            const u64* b1 = reinterpret_cast<const u64*>(s_buf + (cc * 4 + 1) * LSEQ + tph * 16);
            const u64* b2 = reinterpret_cast<const u64*>(s_buf + (cc * 4 + 2) * LSEQ + tph * 16);
            const u64* b3 = reinterpret_cast<const u64*>(s_buf + (cc * 4 + 3) * LSEQ + tph * 16);
#pragma unroll
            for (int p = 0; p < 8; p++) {
                acc2[p] = fma2_(b0[p], w0, acc2[p]);
                acc2[p] = fma2_(b1[p], w1, acc2[p]);
                acc2[p] = fma2_(b2[p], w2, acc2[p]);
                acc2[p] = fma2_(b3[p], w3, acc2[p]);
            }
        }
        u64* hdst = reinterpret_cast<u64*>(s_hsT + d * TST + tph * 16);
#pragma unroll
        for (int p = 0; p < 8; p++) hdst[p] = acc2[p];
    }
    __syncthreads();

    for (int l = 0; l < 2; l++) {
        const int blk = dir * 2 + l;

        // ---- block rmsnorm partials + in_proj A pack (both read hsT) ---------
        {
            float s = 0.f;
#pragma unroll
            for (int q = 0; q < 16; q++) {
                float v = s_hsT[(warp * 16 + q) * TST + lane];
                s += v * v;
            }
            s_red[warp * 32 + lane] = s;
        }
        // pack hs fragments -> bf16 hi/lo, fragment-ordered (hi: 0..2047, lo: +2048)
        {
#pragma unroll
            for (int kk = 0; kk < 2; kk++) {
                int km = warp + kk * 8;         // 0..15 = kc*2 + m
                int kc = km >> 1, m = km & 1;
#pragma unroll
                for (int r = 0; r < 4; r++) {
                    int tt = m * 16 + tb + (r & 1) * 8;
                    int k  = kc * 16 + 2 * kb + (r >> 1) * 8;
                    float v0 = s_hsT[k * TST + tt];
                    float v1 = s_hsT[(k + 1) * TST + tt];
                    unsigned hi, lo;
                    bsplit(v0, v1, hi, lo);
                    s_apk[km * 128 + lane * 4 + r]        = hi;
                    s_apk[2048 + km * 128 + lane * 4 + r] = lo;
                }
            }
        }
        __syncthreads();
        if (tid < 32) {
            float s = 0.f;
#pragma unroll
            for (int w = 0; w < 8; w++) s += s_red[w * 32 + tid];
            s_inv[tid] = rsqrtf(s * (1.f / DM) + EPS);
        }
        __syncthreads();

        // ---- in_proj via bf16 tensor cores (3-pass, packed A): ---------------
        {
            const unsigned* Wf = g_ipf + (size_t)blk * (IP_NT * IP_KC * 128);
            float dacc[9][2][4];
#pragma unroll
            for (int j = 0; j < 9; j++)
#pragma unroll
                for (int m = 0; m < 2; m++)
#pragma unroll
                    for (int q = 0; q < 4; q++) dacc[j][m][q] = 0.f;

#pragma unroll 1
            for (int kc = 0; kc < IP_KC; kc++) {
                uint4 ah[2], al[2];
#pragma unroll
                for (int m = 0; m < 2; m++) {
                    int km = kc * 2 + m;
                    ah[m] = *reinterpret_cast<const uint4*>(s_apk + km * 128 + lane * 4);
                    al[m] = *reinterpret_cast<const uint4*>(s_apk + 2048 + km * 128 + lane * 4);
                }
#pragma unroll
                for (int j = 0; j < 9; j++) {
                    int n = warp + j * 8;
                    if (n < IP_NT) {
                        uint4 bf = *reinterpret_cast<const uint4*>(
                            Wf + ((size_t)(n * IP_KC + kc)) * 128 + lane * 4);
#pragma unroll
                        for (int m = 0; m < 2; m++) {
                            mma_bf16(dacc[j][m], &ah[m].x, bf.x, bf.y);
                            mma_bf16(dacc[j][m], &ah[m].x, bf.z, bf.w);
                            mma_bf16(dacc[j][m], &al[m].x, bf.x, bf.y);
                        }
                    }
                }
            }
            // epilogue: scale rows by inv[t], store to zx
#pragma unroll
            for (int j = 0; j < 9; j++) {
                int n = warp + j * 8;
                if (n < IP_NT) {
#pragma unroll
                    for (int m = 0; m < 2; m++) {
                        int t0 = m * 16 + tb;
                        float i0 = s_inv[t0], i1 = s_inv[t0 + 8];
                        int e0 = n * 8 + 2 * kb;
                        float2 v0 = make_float2(dacc[j][m][0] * i0, dacc[j][m][1] * i0);
                        float2 v1 = make_float2(dacc[j][m][2] * i1, dacc[j][m][3] * i1);
                        *reinterpret_cast<float2*>(s_zx + t0 * EPROJ + e0) = v0;
                        *reinterpret_cast<float2*>(s_zx + (t0 + 8) * EPROJ + e0) = v1;
                    }
                }
            }
        }
        __syncthreads();

        // ---- dt/dA (256 threads == 32 t * 8 heads) + conv boundary pre-reads --
        {
            int t = tid >> 3, h = tid & 7;
            float v  = s_zx[t * EPROJ + DIN + CDIM + h] + dtb[blk * NH + h];
            float sp = (v > 20.f) ? v : log1pf(__expf(v));
            s_dt[t * NH + h] = sp;
            s_dA[t * NH + h] = __expf(-__expf(alog[blk * NH + h]) * sp);
        }
        float pre[2][3];
        {
            int nb = 0;
            for (int u = tid; u < 2 * CDIM; u += NT) {
                if (u >= CDIM) {
                    float* col = s_zx + DIN + (u - CDIM);
                    pre[nb][0] = col[13 * EPROJ];
                    pre[nb][1] = col[14 * EPROJ];
                    pre[nb][2] = col[15 * EPROJ];
                    nb++;
                }
            }
        }
        __syncthreads();

        // ---- causal depthwise conv (k=4) + silu, (c, t-half) units ------------
        {
            int nb = 0;
            for (int u = tid; u < 2 * CDIM; u += NT) {
                int half = (u >= CDIM);
                int c = half ? u - CDIM : u;
                float4 w4 = *reinterpret_cast<const float4*>(cw + ((size_t)blk * CDIM + c) * 4);
                float bb  = cb[blk * CDIM + c];
                float x0, x1, x2;
                if (half) { x0 = pre[nb][0]; x1 = pre[nb][1]; x2 = pre[nb][2]; nb++; }
                else      { x0 = 0.f; x1 = 0.f; x2 = 0.f; }
                float* col = s_zx + DIN + c + (half ? 16 * EPROJ : 0);
#pragma unroll
                for (int tt = 0; tt < 16; tt++) {
                    float xc = col[tt * EPROJ];
                    float o  = fmaf(w4.x, x0, fmaf(w4.y, x1, fmaf(w4.z, x2, fmaf(w4.w, xc, bb))));
                    col[tt * EPROJ] = o * sigmoidf_(o);
                    x0 = x1; x1 = x2; x2 = xc;
                }
            }
        }
        __syncthreads();

        // ---- SSM scan (+ fused gate): thread = (head, p) ----------------------
        {
            int h = tid >> 5;
            u64 st2[NH];
#pragma unroll
            for (int n = 0; n < 8; n++) st2[n] = 0ull;
            float dskip = Dp[blk * NH + h];
            for (int t = 0; t < LSEQ; t++) {
                float* row = s_zx + t * EPROJ;
                float dAv = s_dA[t * NH + h];
                float dtv = s_dt[t * NH + h];
                float xv  = row[DIN + tid];
                u64 dA2  = dup2(dAv);
                u64 dtx2 = dup2(dtv * xv);
                const ulonglong2* Bp = reinterpret_cast<const ulonglong2*>(row + 2 * DIN);
                const ulonglong2* Cp = reinterpret_cast<const ulonglong2*>(row + 2 * DIN + DST);
                u64 y2 = 0ull;
#pragma unroll
                for (int q = 0; q < 4; q++) {
                    ulonglong2 b2 = Bp[q];
                    ulonglong2 c2 = Cp[q];
                    st2[2*q]   = fma2_(st2[2*q],   dA2, mul2_(dtx2, b2.x));
                    y2         = fma2_(st2[2*q],   c2.x, y2);
                    st2[2*q+1] = fma2_(st2[2*q+1], dA2, mul2_(dtx2, b2.y));
                    y2         = fma2_(st2[2*q+1], c2.y, y2);
                }
                float ylo, yhi;
                upk2(y2, ylo, yhi);
                float yv = fmaf(dskip, xv, ylo + yhi);
                float z  = row[tid];
                row[DIN + tid] = yv * z * sigmoidf_(z);   // fused gate
            }
        }
        __syncthreads();

        // ---- mixer rmsnorm partials + out_proj A pack (z cols now dead) -------
        {
            int t = tid >> 3, part = tid & 7;
            const float4* gp = reinterpret_cast<const float4*>(s_zx + t * EPROJ + DIN + part * 32);
            float s = 0.f;
#pragma unroll
            for (int q = 0; q < 8; q++) {
                float4 v = gp[q];
                s += v.x * v.x + v.y * v.y + v.z * v.z + v.w * v.w;
            }
            s += __shfl_xor_sync(0xffffffffu, s, 1);
            s += __shfl_xor_sync(0xffffffffu, s, 2);
            s += __shfl_xor_sync(0xffffffffu, s, 4);
            if (part == 0) s_inv2[t] = rsqrtf(s * (1.f / DIN) + EPS);
        }
        // pack gated-g fragments -> bf16 hi/lo into dead z region
        {
#pragma unroll
            for (int kk = 0; kk < 4; kk++) {
                int km = warp + kk * 8;         // 0..31 = kc*2 + m
                int kc = km >> 1, m = km & 1;
#pragma unroll
                for (int r = 0; r < 4; r++) {
                    int tt = m * 16 + tb + (r & 1) * 8;
                    int e  = DIN + kc * 16 + 2 * kb + (r >> 1) * 8;
                    float2 v = *reinterpret_cast<const float2*>(s_zx + tt * EPROJ + e);
                    unsigned hi, lo;
                    bsplit(v.x, v.y, hi, lo);
                    int w = km * 128 + lane * 4 + r;
                    s_zxw[ZIDX(w)]        = hi;
                    s_zxw[ZIDX(4096 + w)] = lo;
                }
            }
        }
        __syncthreads();

        // ---- out_proj via bf16 tensor cores (3-pass, packed A) + residual -----
        {
            const unsigned* Wf = g_opf + (size_t)blk * (OP_NT * OP_KC * 128);
            float dacc[2][2][4];
#pragma unroll
            for (int j = 0; j < 2; j++)
#pragma unroll
                for (int m = 0; m < 2; m++)
#pragma unroll
                    for (int q = 0; q < 4; q++) dacc[j][m][q] = 0.f;

#pragma unroll 1
            for (int kc = 0; kc < OP_KC; kc++) {
                uint4 ah[2], al[2];
#pragma unroll
                for (int m = 0; m < 2; m++) {
                    int w0 = (kc * 2 + m) * 128 + lane * 4;
                    ah[m] = *reinterpret_cast<const uint4*>(s_zxw + ZIDX(w0));
                    al[m] = *reinterpret_cast<const uint4*>(s_zxw + ZIDX(4096 + w0));
                }
#pragma unroll
                for (int j = 0; j < 2; j++) {
                    int n = warp + j * 8;
                    uint4 bf = *reinterpret_cast<const uint4*>(
                        Wf + ((size_t)(n * OP_KC + kc)) * 128 + lane * 4);
#pragma unroll
                    for (int m = 0; m < 2; m++) {
                        mma_bf16(dacc[j][m], &ah[m].x, bf.x, bf.y);
                        mma_bf16(dacc[j][m], &ah[m].x, bf.z, bf.w);
                        mma_bf16(dacc[j][m], &al[m].x, bf.x, bf.y);
                    }
                }
            }
            // epilogue: hsT[d][t] += inv2[t] * D[t][d]
#pragma unroll
            for (int j = 0; j < 2; j++) {
                int n = warp + j * 8;
#pragma unroll
                for (int m = 0; m < 2; m++) {
                    int t0 = m * 16 + tb;
                    float i0 = s_inv2[t0], i1 = s_inv2[t0 + 8];
                    int d0 = n * 8 + 2 * kb;
                    s_hsT[d0 * TST + t0]           += dacc[j][m][0] * i0;
                    s_hsT[(d0 + 1) * TST + t0]     += dacc[j][m][1] * i0;
                    s_hsT[d0 * TST + t0 + 8]       += dacc[j][m][2] * i1;
                    s_hsT[(d0 + 1) * TST + t0 + 8] += dacc[j][m][3] * i1;
                }
            }
        }
        __syncthreads();
    } // layer

    // ---- final rmsnorm(norm_f) over d ------------------------------------------
    {
        float s = 0.f;
#pragma unroll
        for (int q = 0; q < 16; q++) {
            float v = s_hsT[(warp * 16 + q) * TST + lane];
            s += v * v;
        }
        s_red[warp * 32 + lane] = s;
    }
    __syncthreads();
    if (tid < 32) {
        float s = 0.f;
#pragma unroll
        for (int w = 0; w < 8; w++) s += s_red[w * 32 + tid];
        s_inv[tid] = rsqrtf(s * (1.f / DM) + EPS);
    }
    __syncthreads();

    // ---- L-weighted accumulate -> g_A ------------------------------------------
    if (tid < DM) {
        const float* hrow = s_hsT + tid * TST;
        float s = 0.f;
#pragma unroll
        for (int t = 0; t < LSEQ; t++) {
            float wl = olw[dir ? (LSEQ - 1 - t) : t];
            s = fmaf(wl * s_inv[t], hrow[t], s);
        }
        g_A[((size_t)b * 2 + dir) * DM + tid] = s * nfw[dir * DM + tid];
    }
}

extern "C" void kernel_launch(void* const* d_in, const int* in_sizes, int n_in,
                              void* d_out, int out_size) {
    const float* x      = (const float*)d_in[0];
    const float* buffer = (const float*)d_in[1];
    const float* fiw    = (const float*)d_in[2];
    const float* fib    = (const float*)d_in[3];
    const float* bnw    = (const float*)d_in[4];
    const float* ipw    = (const float*)d_in[5];
    const float* cw     = (const float*)d_in[6];
    const float* cb     = (const float*)d_in[7];
    const float* dtb    = (const float*)d_in[8];
    const float* alog   = (const float*)d_in[9];
    const float* Dp     = (const float*)d_in[10];
    const float* mnw    = (const float*)d_in[11];
    const float* opw    = (const float*)d_in[12];
    const float* nfw    = (const float*)d_in[13];
    const float* fow    = (const float*)d_in[14];
    const float* fob    = (const float*)d_in[15];
    const float* olw    = (const float*)d_in[16];
    const float* olb    = (const float*)d_in[17];
    float* out = (float*)d_out;

    int B = in_sizes[0] / CIN;   // 1024
    size_t smem_bytes = (size_t)SMEM_FLOATS * sizeof(float);

    cudaFuncSetAttribute(mamba_actor_kernel,
                         cudaFuncAttributeMaxDynamicSharedMemorySize,
                         (int)smem_bytes);

    int prep_total = IPF_N + OPF_N;
    prep_weights<<<(prep_total + 255) / 256, 256>>>(ipw, bnw, opw, mnw);

    mamba_actor_kernel<<<2 * B, NT, smem_bytes>>>(
        x, buffer, fiw, fib, cw, cb, dtb, alog,
        Dp, nfw, olw, out);

    finalize_kernel<<<(B * COUT + 255) / 256, 256>>>(fow, fob, olw, olb, out, B);
}

// round 13
// speedup vs baseline: 1.0680x; 1.0240x over previous
#include <cuda_runtime.h>
#include <math.h>

#define EPS      1e-5f
#define LSEQ     32
#define DM       128
#define CIN      96
#define COUT     12
#define DIN      256
#define DST      16
#define NH       8
#define CDIM     288          // DIN + 2*DST
#define EPROJ    552          // 2*DIN + 2*DST + NH
#define TST      36           // hs transposed stride (conflict-free k-pair loads)
#define NT       256
#define MAXB     1024

#define IP_NT    69           // in_proj n-tiles (552/8)
#define IP_KC    8            // in_proj k16-chunks (128/16)
#define OP_NT    16           // out_proj n-tiles (128/8)
#define OP_KC    16           // out_proj k16-chunks (256/16)

typedef unsigned long long u64;

// device scratch: bf16 hi/lo fragment-packed weights (one 32-bit word = bf16x2)
#define IPF_N (4 * IP_NT * IP_KC * 128)   // 282624 words
#define OPF_N (4 * OP_NT * OP_KC * 128)   // 131072 words
__device__ unsigned g_ipf[IPF_N];
__device__ unsigned g_opf[OPF_N];
__device__ float g_A[(size_t)MAXB * 2 * DM];

// shared memory layout (floats)
// OFF_APK: 4096 words, in_proj packed A fragments (hi:0..2047, lo:2048..4095).
//          Overlays s_buf (stage0/fc_in only, dead afterwards).
#define OFF_APK   0
#define OFF_HST   4096                       // 128*36 = 4608
#define OFF_ZX    (OFF_HST + DM*TST)         // 32*552 = 17664
#define OFF_DT    (OFF_ZX + LSEQ*EPROJ)      // 256
#define OFF_DA    (OFF_DT + LSEQ*NH)         // 256
#define OFF_INV   (OFF_DA + LSEQ*NH)         // 32
#define OFF_INV2  (OFF_INV + LSEQ)           // 32
#define OFF_RED   (OFF_INV2 + LSEQ)          // 256
#define SMEM_FLOATS (OFF_RED + NT)           // 27200 floats = 108800 B

// out_proj packed A lives in dead z-columns of s_zx: word w -> row w>>8, col w&255
#define ZIDX(w) ((((w) >> 8) * EPROJ) + ((w) & 255))

__device__ __forceinline__ float sigmoidf_(float v) {
    return 1.f / (1.f + __expf(-v));
}
__device__ __forceinline__ u64 pk2(float lo, float hi) {
    u64 r; asm("mov.b64 %0,{%1,%2};" : "=l"(r) : "f"(lo), "f"(hi)); return r;
}
__device__ __forceinline__ u64 dup2(float v) { return pk2(v, v); }
__device__ __forceinline__ void upk2(u64 a, float& lo, float& hi) {
    asm("mov.b64 {%0,%1},%2;" : "=f"(lo), "=f"(hi) : "l"(a));
}
__device__ __forceinline__ u64 fma2_(u64 a, u64 b, u64 c) {
    u64 d; asm("fma.rn.f32x2 %0,%1,%2,%3;" : "=l"(d) : "l"(a), "l"(b), "l"(c)); return d;
}
__device__ __forceinline__ u64 mul2_(u64 a, u64 b) {
    u64 d; asm("mul.rn.f32x2 %0,%1,%2;" : "=l"(d) : "l"(a), "l"(b)); return d;
}

// split (v0, v1) -> packed bf16x2 hi (rz-trunc) and lo (rn of residual)
__device__ __forceinline__ void bsplit(float v0, float v1, unsigned& hi, unsigned& lo) {
    unsigned u0 = __float_as_uint(v0), u1 = __float_as_uint(v1);
    asm("prmt.b32 %0,%1,%2,0x7632;" : "=r"(hi) : "r"(u0), "r"(u1));
    float h0 = __uint_as_float(u0 & 0xffff0000u);
    float h1 = __uint_as_float(u1 & 0xffff0000u);
    asm("cvt.rn.bf16x2.f32 %0,%1,%2;" : "=r"(lo) : "f"(v1 - h1), "f"(v0 - h0));
}
__device__ __forceinline__ void mma_bf16(float* d, const unsigned* a,
                                         unsigned b0, unsigned b1) {
    asm volatile(
        "mma.sync.aligned.m16n8k16.row.col.f32.bf16.bf16.f32 "
        "{%0,%1,%2,%3},{%4,%5,%6,%7},{%8,%9},{%0,%1,%2,%3};"
        : "+f"(d[0]), "+f"(d[1]), "+f"(d[2]), "+f"(d[3])
        : "r"(a[0]), "r"(a[1]), "r"(a[2]), "r"(a[3]), "r"(b0), "r"(b1));
}

// ---- prep: fold norms, bf16 hi/lo split, B-fragment lane order --------------
__global__ void prep_weights(const float* __restrict__ ipw,
                             const float* __restrict__ bnw,
                             const float* __restrict__ opw,
                             const float* __restrict__ mnw) {
    int i = blockIdx.x * blockDim.x + threadIdx.x;
    if (i < IPF_N) {
        int blk = i / (IP_NT * IP_KC * 128);
        int r   = i - blk * (IP_NT * IP_KC * 128);
        int n   = r / (IP_KC * 128);
        int q   = r - n * (IP_KC * 128);
        int kc  = q >> 7;
        int rem = q & 127;
        int lane = rem >> 2, comp = rem & 3;
        int g = lane >> 2, c = lane & 3;
        int e  = n * 8 + g;
        int k0 = kc * 16 + 2 * c + ((comp & 1) ? 8 : 0);
        float v0 = ipw[((size_t)blk * EPROJ + e) * DM + k0]     * bnw[blk * DM + k0];
        float v1 = ipw[((size_t)blk * EPROJ + e) * DM + k0 + 1] * bnw[blk * DM + k0 + 1];
        unsigned hi, lo;
        bsplit(v0, v1, hi, lo);
        g_ipf[i] = (comp < 2) ? hi : lo;
    } else if (i < IPF_N + OPF_N) {
        int j   = i - IPF_N;
        int blk = j >> 15;
        int r   = j & 32767;
        int n   = r >> 11;
        int q   = r & 2047;
        int kc  = q >> 7;
        int rem = q & 127;
        int lane = rem >> 2, comp = rem & 3;
        int g = lane >> 2, c = lane & 3;
        int d  = n * 8 + g;
        int e0 = kc * 16 + 2 * c + ((comp & 1) ? 8 : 0);
        float v0 = opw[((size_t)blk * DM + d) * DIN + e0]     * mnw[blk * DIN + e0];
        float v1 = opw[((size_t)blk * DM + d) * DIN + e0 + 1] * mnw[blk * DIN + e0 + 1];
        unsigned hi, lo;
        bsplit(v0, v1, hi, lo);
        g_opf[j] = (comp < 2) ? hi : lo;
    }
}

// ---- finalize ----------------------------------------------------------------
__global__ void finalize_kernel(const float* __restrict__ fow,
                                const float* __restrict__ fob,
                                const float* __restrict__ olw,
                                const float* __restrict__ olb,
                                float* __restrict__ out, int B) {
    int idx = blockIdx.x * blockDim.x + threadIdx.x;
    if (idx >= B * COUT) return;
    int b = idx / COUT, o = idx - b * COUT;
    float Swl = 0.f;
#pragma unroll
    for (int t = 0; t < LSEQ; t++) Swl += olw[t];
    const float* A0 = g_A + (size_t)b * 2 * DM;
    float acc = 0.f;
#pragma unroll 4
    for (int d = 0; d < DM; d++) acc = fmaf(fow[o * DM + d], A0[d] + A0[DM + d], acc);
    out[idx] = acc + fob[o] * Swl + olb[0];
}

// ---- main: one CTA per (batch, direction) -------------------------------------
__global__ void __launch_bounds__(NT, 2) mamba_actor_kernel(
    const float* __restrict__ x,        // (B, 96)
    const float* __restrict__ buffer,   // (B, 96, 32)
    const float* __restrict__ fiw,      // (128, 96)
    const float* __restrict__ fib,      // (128,)
    const float* __restrict__ cw,       // (4, 288, 4)
    const float* __restrict__ cb,       // (4, 288)
    const float* __restrict__ dtb,      // (4, 8)
    const float* __restrict__ alog,     // (4, 8)
    const float* __restrict__ Dp,       // (4, 8)
    const float* __restrict__ nfw,      // (2, 128)
    const float* __restrict__ olw,      // (1, 32)
    float* __restrict__ out)
{
    extern __shared__ float sm[];
    float*    s_buf  = sm + OFF_APK;   // stage0/fc_in only
    unsigned* s_apk  = reinterpret_cast<unsigned*>(sm + OFF_APK);
    float*    s_hsT  = sm + OFF_HST;   // [k][t], stride TST
    float*    s_zx   = sm + OFF_ZX;    // [t][e], stride EPROJ
    unsigned* s_zxw  = reinterpret_cast<unsigned*>(sm + OFF_ZX);
    float*    s_dt   = sm + OFF_DT;
    float*    s_dA   = sm + OFF_DA;
    float*    s_inv  = sm + OFF_INV;
    float*    s_inv2 = sm + OFF_INV2;
    float*    s_red  = sm + OFF_RED;

    const int B    = gridDim.x >> 1;
    const int b    = blockIdx.x >> 1;
    const int dir  = blockIdx.x & 1;
    const int tid  = threadIdx.x;
    const int lane = tid & 31;
    const int warp = tid >> 5;
    const int kb   = lane & 3;      // c: thread-in-group
    const int tb   = lane >> 2;     // g: group id (row)

    // ---- Stage 0: shifted buffer -> smem (dir-flipped) + buf output ----------
    {
        const float* bsrc = buffer + (size_t)b * CIN * LSEQ;
        const float* xsrc = x + (size_t)b * CIN;
        float* bdst = out + (size_t)B * COUT + (size_t)b * CIN * LSEQ;
        for (int idx = tid; idx < CIN * LSEQ; idx += NT) {
            int c = idx >> 5, l = idx & 31;
            float v = (l < LSEQ - 1) ? bsrc[c * LSEQ + l + 1] : xsrc[c];
            int ls = dir ? (LSEQ - 1 - l) : l;
            s_buf[c * LSEQ + ls] = v;
            if (dir == 0) bdst[idx] = v;
        }
    }
    __syncthreads();

    // ---- fc_in (f32x2): thread = (d, t-half) ---------------------------------
    {
        int d   = tid >> 1;
        int tph = tid & 1;
        u64 acc2[8];
        u64 bias = dup2(fib[d]);
#pragma unroll
        for (int p = 0; p < 8; p++) acc2[p] = bias;
        const float4* wrow = reinterpret_cast<const float4*>(fiw + d * CIN);
#pragma unroll 2
        for (int cc = 0; cc < CIN / 4; cc++) {
            float4 w4 = wrow[cc];
            u64 w0 = dup2(w4.x), w1 = dup2(w4.y), w2 = dup2(w4.z), w3 = dup2(w4.w);
            const u64* b0 = reinterpret_cast<const u64*>(s_buf + (cc * 4 + 0) * LSEQ + tph * 16);
            const u64* b1 = reinterpret_cast<const u64*>(s_buf + (cc * 4 + 1) * LSEQ + tph * 16);
            const u64* b2 = reinterpret_cast<const u64*>(s_buf + (cc * 4 + 2) * LSEQ + tph * 16);
            const u64* b3 = reinterpret_cast<const u64*>(s_buf + (cc * 4 + 3) * LSEQ + tph * 16);
#pragma unroll
            for (int p = 0; p < 8; p++) {
                acc2[p] = fma2_(b0[p], w0, acc2[p]);
                acc2[p] = fma2_(b1[p], w1, acc2[p]);
                acc2[p] = fma2_(b2[p], w2, acc2[p]);
                acc2[p] = fma2_(b3[p], w3, acc2[p]);
            }
        }
        u64* hdst = reinterpret_cast<u64*>(s_hsT + d * TST + tph * 16);
#pragma unroll
        for (int p = 0; p < 8; p++) hdst[p] = acc2[p];
    }
    __syncthreads();

    for (int l = 0; l < 2; l++) {
        const int blk = dir * 2 + l;

        // ---- block rmsnorm partials + in_proj A pack (both read hsT) ---------
        {
            float s = 0.f;
#pragma unroll
            for (int q = 0; q < 16; q++) {
                float v = s_hsT[(warp * 16 + q) * TST + lane];
                s += v * v;
            }
            s_red[warp * 32 + lane] = s;
        }
        // pack hs fragments -> bf16 hi/lo, fragment-ordered (hi: 0..2047, lo: +2048)
        {
#pragma unroll
            for (int kk = 0; kk < 2; kk++) {
                int km = warp + kk * 8;         // 0..15 = kc*2 + m
                int kc = km >> 1, m = km & 1;
#pragma unroll
                for (int r = 0; r < 4; r++) {
                    int tt = m * 16 + tb + (r & 1) * 8;
                    int k  = kc * 16 + 2 * kb + (r >> 1) * 8;
                    float v0 = s_hsT[k * TST + tt];
                    float v1 = s_hsT[(k + 1) * TST + tt];
                    unsigned hi, lo;
                    bsplit(v0, v1, hi, lo);
                    s_apk[km * 128 + lane * 4 + r]        = hi;
                    s_apk[2048 + km * 128 + lane * 4 + r] = lo;
                }
            }
        }
        __syncthreads();
        if (tid < 32) {
            float s = 0.f;
#pragma unroll
            for (int w = 0; w < 8; w++) s += s_red[w * 32 + tid];
            s_inv[tid] = rsqrtf(s * (1.f / DM) + EPS);
        }
        __syncthreads();

        // ---- in_proj via bf16 tensor cores (3-pass, packed A) -----------------
        // MMA issue reordered: j-groups of 3, pass-by-pass across 6 chains
        {
            const unsigned* Wf = g_ipf + (size_t)blk * (IP_NT * IP_KC * 128);
            float dacc[9][2][4];
#pragma unroll
            for (int j = 0; j < 9; j++)
#pragma unroll
                for (int m = 0; m < 2; m++)
#pragma unroll
                    for (int q = 0; q < 4; q++) dacc[j][m][q] = 0.f;

#pragma unroll 1
            for (int kc = 0; kc < IP_KC; kc++) {
                uint4 ah[2], al[2];
#pragma unroll
                for (int m = 0; m < 2; m++) {
                    int km = kc * 2 + m;
                    ah[m] = *reinterpret_cast<const uint4*>(s_apk + km * 128 + lane * 4);
                    al[m] = *reinterpret_cast<const uint4*>(s_apk + 2048 + km * 128 + lane * 4);
                }
#pragma unroll
                for (int jg = 0; jg < 3; jg++) {
                    uint4 bf[3];
#pragma unroll
                    for (int u = 0; u < 3; u++) {
                        int n = warp + (jg * 3 + u) * 8;
                        int nn = (n < IP_NT) ? n : 0;
                        bf[u] = *reinterpret_cast<const uint4*>(
                            Wf + ((size_t)(nn * IP_KC + kc)) * 128 + lane * 4);
                    }
                    // pass 0: Ahi x Bhi — 6 independent chains
#pragma unroll
                    for (int u = 0; u < 3; u++) {
                        int j = jg * 3 + u;
                        if (warp + j * 8 < IP_NT) {
                            mma_bf16(dacc[j][0], &ah[0].x, bf[u].x, bf[u].y);
                            mma_bf16(dacc[j][1], &ah[1].x, bf[u].x, bf[u].y);
                        }
                    }
                    // pass 1: Ahi x Blo
#pragma unroll
                    for (int u = 0; u < 3; u++) {
                        int j = jg * 3 + u;
                        if (warp + j * 8 < IP_NT) {
                            mma_bf16(dacc[j][0], &ah[0].x, bf[u].z, bf[u].w);
                            mma_bf16(dacc[j][1], &ah[1].x, bf[u].z, bf[u].w);
                        }
                    }
                    // pass 2: Alo x Bhi
#pragma unroll
                    for (int u = 0; u < 3; u++) {
                        int j = jg * 3 + u;
                        if (warp + j * 8 < IP_NT) {
                            mma_bf16(dacc[j][0], &al[0].x, bf[u].x, bf[u].y);
                            mma_bf16(dacc[j][1], &al[1].x, bf[u].x, bf[u].y);
                        }
                    }
                }
            }
            // epilogue: scale rows by inv[t], store to zx
#pragma unroll
            for (int j = 0; j < 9; j++) {
                int n = warp + j * 8;
                if (n < IP_NT) {
#pragma unroll
                    for (int m = 0; m < 2; m++) {
                        int t0 = m * 16 + tb;
                        float i0 = s_inv[t0], i1 = s_inv[t0 + 8];
                        int e0 = n * 8 + 2 * kb;
                        float2 v0 = make_float2(dacc[j][m][0] * i0, dacc[j][m][1] * i0);
                        float2 v1 = make_float2(dacc[j][m][2] * i1, dacc[j][m][3] * i1);
                        *reinterpret_cast<float2*>(s_zx + t0 * EPROJ + e0) = v0;
                        *reinterpret_cast<float2*>(s_zx + (t0 + 8) * EPROJ + e0) = v1;
                    }
                }
            }
        }
        __syncthreads();

        // ---- dt/dA (256 threads == 32 t * 8 heads) + conv boundary pre-reads --
        {
            int t = tid >> 3, h = tid & 7;
            float v  = s_zx[t * EPROJ + DIN + CDIM + h] + dtb[blk * NH + h];
            float sp = (v > 20.f) ? v : log1pf(__expf(v));
            s_dt[t * NH + h] = sp;
            s_dA[t * NH + h] = __expf(-__expf(alog[blk * NH + h]) * sp);
        }
        float pre[2][3];
        {
            int nb = 0;
            for (int u = tid; u < 2 * CDIM; u += NT) {
                if (u >= CDIM) {
                    float* col = s_zx + DIN + (u - CDIM);
                    pre[nb][0] = col[13 * EPROJ];
                    pre[nb][1] = col[14 * EPROJ];
                    pre[nb][2] = col[15 * EPROJ];
                    nb++;
                }
            }
        }
        __syncthreads();

        // ---- causal depthwise conv (k=4) + silu, (c, t-half) units ------------
        {
            int nb = 0;
            for (int u = tid; u < 2 * CDIM; u += NT) {
                int half = (u >= CDIM);
                int c = half ? u - CDIM : u;
                float4 w4 = *reinterpret_cast<const float4*>(cw + ((size_t)blk * CDIM + c) * 4);
                float bb  = cb[blk * CDIM + c];
                float x0, x1, x2;
                if (half) { x0 = pre[nb][0]; x1 = pre[nb][1]; x2 = pre[nb][2]; nb++; }
                else      { x0 = 0.f; x1 = 0.f; x2 = 0.f; }
                float* col = s_zx + DIN + c + (half ? 16 * EPROJ : 0);
#pragma unroll
                for (int tt = 0; tt < 16; tt++) {
                    float xc = col[tt * EPROJ];
                    float o  = fmaf(w4.x, x0, fmaf(w4.y, x1, fmaf(w4.z, x2, fmaf(w4.w, xc, bb))));
                    col[tt * EPROJ] = o * sigmoidf_(o);
                    x0 = x1; x1 = x2; x2 = xc;
                }
            }
        }
        __syncthreads();

        // ---- SSM scan (+ fused gate): thread = (head, p) ----------------------
        {
            int h = tid >> 5;
            u64 st2[NH];
#pragma unroll
            for (int n = 0; n < 8; n++) st2[n] = 0ull;
            float dskip = Dp[blk * NH + h];
            for (int t = 0; t < LSEQ; t++) {
                float* row = s_zx + t * EPROJ;
                float dAv = s_dA[t * NH + h];
                float dtv = s_dt[t * NH + h];
                float xv  = row[DIN + tid];
                u64 dA2  = dup2(dAv);
                u64 dtx2 = dup2(dtv * xv);
                const ulonglong2* Bp = reinterpret_cast<const ulonglong2*>(row + 2 * DIN);
                const ulonglong2* Cp = reinterpret_cast<const ulonglong2*>(row + 2 * DIN + DST);
                u64 y2 = 0ull;
#pragma unroll
                for (int q = 0; q < 4; q++) {
                    ulonglong2 b2 = Bp[q];
                    ulonglong2 c2 = Cp[q];
                    st2[2*q]   = fma2_(st2[2*q],   dA2, mul2_(dtx2, b2.x));
                    y2         = fma2_(st2[2*q],   c2.x, y2);
                    st2[2*q+1] = fma2_(st2[2*q+1], dA2, mul2_(dtx2, b2.y));
                    y2         = fma2_(st2[2*q+1], c2.y, y2);
                }
                float ylo, yhi;
                upk2(y2, ylo, yhi);
                float yv = fmaf(dskip, xv, ylo + yhi);
                float z  = row[tid];
                row[DIN + tid] = yv * z * sigmoidf_(z);   // fused gate
            }
        }
        __syncthreads();

        // ---- mixer rmsnorm partials + out_proj A pack (z cols now dead) -------
        {
            int t = tid >> 3, part = tid & 7;
            const float4* gp = reinterpret_cast<const float4*>(s_zx + t * EPROJ + DIN + part * 32);
            float s = 0.f;
#pragma unroll
            for (int q = 0; q < 8; q++) {
                float4 v = gp[q];
                s += v.x * v.x + v.y * v.y + v.z * v.z + v.w * v.w;
            }
            s += __shfl_xor_sync(0xffffffffu, s, 1);
            s += __shfl_xor_sync(0xffffffffu, s, 2);
            s += __shfl_xor_sync(0xffffffffu, s, 4);
            if (part == 0) s_inv2[t] = rsqrtf(s * (1.f / DIN) + EPS);
        }
        // pack gated-g fragments -> bf16 hi/lo into dead z region
        {
#pragma unroll
            for (int kk = 0; kk < 4; kk++) {
                int km = warp + kk * 8;         // 0..31 = kc*2 + m
                int kc = km >> 1, m = km & 1;
#pragma unroll
                for (int r = 0; r < 4; r++) {
                    int tt = m * 16 + tb + (r & 1) * 8;
                    int e  = DIN + kc * 16 + 2 * kb + (r >> 1) * 8;
                    float2 v = *reinterpret_cast<const float2*>(s_zx + tt * EPROJ + e);
                    unsigned hi, lo;
                    bsplit(v.x, v.y, hi, lo);
                    int w = km * 128 + lane * 4 + r;
                    s_zxw[ZIDX(w)]        = hi;
                    s_zxw[ZIDX(4096 + w)] = lo;
                }
            }
        }
        __syncthreads();

        // ---- out_proj via bf16 tensor cores (3-pass, packed A) + residual -----
        // MMA issue reordered: pass-by-pass across 4 chains
        {
            const unsigned* Wf = g_opf + (size_t)blk * (OP_NT * OP_KC * 128);
            float dacc[2][2][4];
#pragma unroll
            for (int j = 0; j < 2; j++)
#pragma unroll
                for (int m = 0; m < 2; m++)
#pragma unroll
                    for (int q = 0; q < 4; q++) dacc[j][m][q] = 0.f;

#pragma unroll 1
            for (int kc = 0; kc < OP_KC; kc++) {
                uint4 ah[2], al[2];
#pragma unroll
                for (int m = 0; m < 2; m++) {
                    int w0 = (kc * 2 + m) * 128 + lane * 4;
                    ah[m] = *reinterpret_cast<const uint4*>(s_zxw + ZIDX(w0));
                    al[m] = *reinterpret_cast<const uint4*>(s_zxw + ZIDX(4096 + w0));
                }
                uint4 bf0 = *reinterpret_cast<const uint4*>(
                    Wf + ((size_t)((warp + 0) * OP_KC + kc)) * 128 + lane * 4);
                uint4 bf1 = *reinterpret_cast<const uint4*>(
                    Wf + ((size_t)((warp + 8) * OP_KC + kc)) * 128 + lane * 4);
                // pass 0: Ahi x Bhi — 4 chains
                mma_bf16(dacc[0][0], &ah[0].x, bf0.x, bf0.y);
                mma_bf16(dacc[0][1], &ah[1].x, bf0.x, bf0.y);
                mma_bf16(dacc[1][0], &ah[0].x, bf1.x, bf1.y);
                mma_bf16(dacc[1][1], &ah[1].x, bf1.x, bf1.y);
                // pass 1: Ahi x Blo
                mma_bf16(dacc[0][0], &ah[0].x, bf0.z, bf0.w);
                mma_bf16(dacc[0][1], &ah[1].x, bf0.z, bf0.w);
                mma_bf16(dacc[1][0], &ah[0].x, bf1.z, bf1.w);
                mma_bf16(dacc[1][1], &ah[1].x, bf1.z, bf1.w);
                // pass 2: Alo x Bhi
                mma_bf16(dacc[0][0], &al[0].x, bf0.x, bf0.y);
                mma_bf16(dacc[0][1], &al[1].x, bf0.x, bf0.y);
                mma_bf16(dacc[1][0], &al[0].x, bf1.x, bf1.y);
                mma_bf16(dacc[1][1], &al[1].x, bf1.x, bf1.y);
            }
            // epilogue: hsT[d][t] += inv2[t] * D[t][d]
#pragma unroll
            for (int j = 0; j < 2; j++) {
                int n = warp + j * 8;
#pragma unroll
                for (int m = 0; m < 2; m++) {
                    int t0 = m * 16 + tb;
                    float i0 = s_inv2[t0], i1 = s_inv2[t0 + 8];
                    int d0 = n * 8 + 2 * kb;
                    s_hsT[d0 * TST + t0]           += dacc[j][m][0] * i0;
                    s_hsT[(d0 + 1) * TST + t0]     += dacc[j][m][1] * i0;
                    s_hsT[d0 * TST + t0 + 8]       += dacc[j][m][2] * i1;
                    s_hsT[(d0 + 1) * TST + t0 + 8] += dacc[j][m][3] * i1;
                }
            }
        }
        __syncthreads();
    } // layer

    // ---- final rmsnorm(norm_f) over d ------------------------------------------
    {
        float s = 0.f;
#pragma unroll
        for (int q = 0; q < 16; q++) {
            float v = s_hsT[(warp * 16 + q) * TST + lane];
            s += v * v;
        }
        s_red[warp * 32 + lane] = s;
    }
    __syncthreads();
    if (tid < 32) {
        float s = 0.f;
#pragma unroll
        for (int w = 0; w < 8; w++) s += s_red[w * 32 + tid];
        s_inv[tid] = rsqrtf(s * (1.f / DM) + EPS);
    }
    __syncthreads();

    // ---- L-weighted accumulate -> g_A ------------------------------------------
    if (tid < DM) {
        const float* hrow = s_hsT + tid * TST;
        float s = 0.f;
#pragma unroll
        for (int t = 0; t < LSEQ; t++) {
            float wl = olw[dir ? (LSEQ - 1 - t) : t];
            s = fmaf(wl * s_inv[t], hrow[t], s);
        }
        g_A[((size_t)b * 2 + dir) * DM + tid] = s * nfw[dir * DM + tid];
    }
}

extern "C" void kernel_launch(void* const* d_in, const int* in_sizes, int n_in,
                              void* d_out, int out_size) {
    const float* x      = (const float*)d_in[0];
    const float* buffer = (const float*)d_in[1];
    const float* fiw    = (const float*)d_in[2];
    const float* fib    = (const float*)d_in[3];
    const float* bnw    = (const float*)d_in[4];
    const float* ipw    = (const float*)d_in[5];
    const float* cw     = (const float*)d_in[6];
    const float* cb     = (const float*)d_in[7];
    const float* dtb    = (const float*)d_in[8];
    const float* alog   = (const float*)d_in[9];
    const float* Dp     = (const float*)d_in[10];
    const float* mnw    = (const float*)d_in[11];
    const float* opw    = (const float*)d_in[12];
    const float* nfw    = (const float*)d_in[13];
    const float* fow    = (const float*)d_in[14];
    const float* fob    = (const float*)d_in[15];
    const float* olw    = (const float*)d_in[16];
    const float* olb    = (const float*)d_in[17];
    float* out = (float*)d_out;

    int B = in_sizes[0] / CIN;   // 1024
    size_t smem_bytes = (size_t)SMEM_FLOATS * sizeof(float);

    cudaFuncSetAttribute(mamba_actor_kernel,
                         cudaFuncAttributeMaxDynamicSharedMemorySize,
                         (int)smem_bytes);

    int prep_total = IPF_N + OPF_N;
    prep_weights<<<(prep_total + 255) / 256, 256>>>(ipw, bnw, opw, mnw);

    mamba_actor_kernel<<<2 * B, NT, smem_bytes>>>(
        x, buffer, fiw, fib, cw, cb, dtb, alog,
        Dp, nfw, olw, out);

    finalize_kernel<<<(B * COUT + 255) / 256, 256>>>(fow, fob, olw, olb, out, B);
}

// round 14
// speedup vs baseline: 1.1562x; 1.0826x over previous
#include <cuda_runtime.h>
#include <cuda_fp16.h>
#include <math.h>

#define EPS      1e-5f
#define LSEQ     32
#define DM       128
#define CIN      96
#define COUT     12
#define DIN      256
#define DST      16
#define NH       8
#define CDIM     288          // DIN + 2*DST
#define EPROJ    552          // 2*DIN + 2*DST + NH
#define TST      36           // hs transposed stride (conflict-free k-pair loads)
#define NT       256
#define MAXB     1024

#define IP_NT    69           // in_proj n-tiles (552/8)
#define IP_KC    8            // in_proj k16-chunks (128/16)
#define OP_NT    16           // out_proj n-tiles (128/8)
#define OP_KC    16           // out_proj k16-chunks (256/16)

typedef unsigned long long u64;

// device scratch: fp16 hi/lo fragment-packed weights (one 32-bit word = f16x2)
#define IPF_N (4 * IP_NT * IP_KC * 128)   // 282624 words
#define OPF_N (4 * OP_NT * OP_KC * 128)   // 131072 words
__device__ unsigned g_ipf[IPF_N];
__device__ unsigned g_opf[OPF_N];
__device__ float g_A[(size_t)MAXB * 2 * DM];

// shared memory layout (floats)
// OFF_APK: in_proj packed A fragments (fp16 hi only, 2048 words).
//          Overlays s_buf (stage0/fc_in only, dead afterwards).
#define OFF_APK   0
#define OFF_HST   4096                       // 128*36 = 4608
#define OFF_ZX    (OFF_HST + DM*TST)         // 32*552 = 17664
#define OFF_DT    (OFF_ZX + LSEQ*EPROJ)      // 256
#define OFF_DA    (OFF_DT + LSEQ*NH)         // 256
#define OFF_INV   (OFF_DA + LSEQ*NH)         // 32
#define OFF_INV2  (OFF_INV + LSEQ)           // 32
#define OFF_RED   (OFF_INV2 + LSEQ)          // 256
#define SMEM_FLOATS (OFF_RED + NT)           // 27200 floats = 108800 B

// out_proj packed A lives in dead z-columns of s_zx: word w -> row w>>8, col w&255
#define ZIDX(w) ((((w) >> 8) * EPROJ) + ((w) & 255))

__device__ __forceinline__ float sigmoidf_(float v) {
    return 1.f / (1.f + __expf(-v));
}
__device__ __forceinline__ u64 pk2(float lo, float hi) {
    u64 r; asm("mov.b64 %0,{%1,%2};" : "=l"(r) : "f"(lo), "f"(hi)); return r;
}
__device__ __forceinline__ u64 dup2(float v) { return pk2(v, v); }
__device__ __forceinline__ void upk2(u64 a, float& lo, float& hi) {
    asm("mov.b64 {%0,%1},%2;" : "=f"(lo), "=f"(hi) : "l"(a));
}
__device__ __forceinline__ u64 fma2_(u64 a, u64 b, u64 c) {
    u64 d; asm("fma.rn.f32x2 %0,%1,%2,%3;" : "=l"(d) : "l"(a), "l"(b), "l"(c)); return d;
}
__device__ __forceinline__ u64 mul2_(u64 a, u64 b) {
    u64 d; asm("mul.rn.f32x2 %0,%1,%2;" : "=l"(d) : "l"(a), "l"(b)); return d;
}

// convert (v0, v1) -> packed f16x2 (v0 in low half, matching MMA fragment order)
__device__ __forceinline__ unsigned hcvt(float v0, float v1) {
    unsigned r;
    asm("cvt.rn.f16x2.f32 %0,%1,%2;" : "=r"(r) : "f"(v1), "f"(v0));
    return r;
}
// split (v0, v1) -> fp16 hi (rn) and lo (rn of residual)
__device__ __forceinline__ void hsplit(float v0, float v1, unsigned& hi, unsigned& lo) {
    hi = hcvt(v0, v1);
    __half2 h = *reinterpret_cast<__half2*>(&hi);
    float h0 = __low2float(h), h1 = __high2float(h);
    lo = hcvt(v0 - h0, v1 - h1);
}
__device__ __forceinline__ void mma_f16(float* d, const unsigned* a,
                                        unsigned b0, unsigned b1) {
    asm volatile(
        "mma.sync.aligned.m16n8k16.row.col.f32.f16.f16.f32 "
        "{%0,%1,%2,%3},{%4,%5,%6,%7},{%8,%9},{%0,%1,%2,%3};"
        : "+f"(d[0]), "+f"(d[1]), "+f"(d[2]), "+f"(d[3])
        : "r"(a[0]), "r"(a[1]), "r"(a[2]), "r"(a[3]), "r"(b0), "r"(b1));
}

// ---- prep: fold norms, fp16 hi/lo split, B-fragment lane order --------------
__global__ void prep_weights(const float* __restrict__ ipw,
                             const float* __restrict__ bnw,
                             const float* __restrict__ opw,
                             const float* __restrict__ mnw) {
    int i = blockIdx.x * blockDim.x + threadIdx.x;
    if (i < IPF_N) {
        int blk = i / (IP_NT * IP_KC * 128);
        int r   = i - blk * (IP_NT * IP_KC * 128);
        int n   = r / (IP_KC * 128);
        int q   = r - n * (IP_KC * 128);
        int kc  = q >> 7;
        int rem = q & 127;
        int lane = rem >> 2, comp = rem & 3;
        int g = lane >> 2, c = lane & 3;
        int e  = n * 8 + g;
        int k0 = kc * 16 + 2 * c + ((comp & 1) ? 8 : 0);
        float v0 = ipw[((size_t)blk * EPROJ + e) * DM + k0]     * bnw[blk * DM + k0];
        float v1 = ipw[((size_t)blk * EPROJ + e) * DM + k0 + 1] * bnw[blk * DM + k0 + 1];
        unsigned hi, lo;
        hsplit(v0, v1, hi, lo);
        g_ipf[i] = (comp < 2) ? hi : lo;
    } else if (i < IPF_N + OPF_N) {
        int j   = i - IPF_N;
        int blk = j >> 15;
        int r   = j & 32767;
        int n   = r >> 11;
        int q   = r & 2047;
        int kc  = q >> 7;
        int rem = q & 127;
        int lane = rem >> 2, comp = rem & 3;
        int g = lane >> 2, c = lane & 3;
        int d  = n * 8 + g;
        int e0 = kc * 16 + 2 * c + ((comp & 1) ? 8 : 0);
        float v0 = opw[((size_t)blk * DM + d) * DIN + e0]     * mnw[blk * DIN + e0];
        float v1 = opw[((size_t)blk * DM + d) * DIN + e0 + 1] * mnw[blk * DIN + e0 + 1];
        unsigned hi, lo;
        hsplit(v0, v1, hi, lo);
        g_opf[j] = (comp < 2) ? hi : lo;
    }
}

// ---- finalize ----------------------------------------------------------------
__global__ void finalize_kernel(const float* __restrict__ fow,
                                const float* __restrict__ fob,
                                const float* __restrict__ olw,
                                const float* __restrict__ olb,
                                float* __restrict__ out, int B) {
    int idx = blockIdx.x * blockDim.x + threadIdx.x;
    if (idx >= B * COUT) return;
    int b = idx / COUT, o = idx - b * COUT;
    float Swl = 0.f;
#pragma unroll
    for (int t = 0; t < LSEQ; t++) Swl += olw[t];
    const float* A0 = g_A + (size_t)b * 2 * DM;
    float acc = 0.f;
#pragma unroll 4
    for (int d = 0; d < DM; d++) acc = fmaf(fow[o * DM + d], A0[d] + A0[DM + d], acc);
    out[idx] = acc + fob[o] * Swl + olb[0];
}

// ---- main: one CTA per (batch, direction) -------------------------------------
__global__ void __launch_bounds__(NT, 2) mamba_actor_kernel(
    const float* __restrict__ x,        // (B, 96)
    const float* __restrict__ buffer,   // (B, 96, 32)
    const float* __restrict__ fiw,      // (128, 96)
    const float* __restrict__ fib,      // (128,)
    const float* __restrict__ cw,       // (4, 288, 4)
    const float* __restrict__ cb,       // (4, 288)
    const float* __restrict__ dtb,      // (4, 8)
    const float* __restrict__ alog,     // (4, 8)
    const float* __restrict__ Dp,       // (4, 8)
    const float* __restrict__ nfw,      // (2, 128)
    const float* __restrict__ olw,      // (1, 32)
    float* __restrict__ out)
{
    extern __shared__ float sm[];
    float*    s_buf  = sm + OFF_APK;   // stage0/fc_in only
    unsigned* s_apk  = reinterpret_cast<unsigned*>(sm + OFF_APK);
    float*    s_hsT  = sm + OFF_HST;   // [k][t], stride TST
    float*    s_zx   = sm + OFF_ZX;    // [t][e], stride EPROJ
    unsigned* s_zxw  = reinterpret_cast<unsigned*>(sm + OFF_ZX);
    float*    s_dt   = sm + OFF_DT;
    float*    s_dA   = sm + OFF_DA;
    float*    s_inv  = sm + OFF_INV;
    float*    s_inv2 = sm + OFF_INV2;
    float*    s_red  = sm + OFF_RED;

    const int B    = gridDim.x >> 1;
    const int b    = blockIdx.x >> 1;
    const int dir  = blockIdx.x & 1;
    const int tid  = threadIdx.x;
    const int lane = tid & 31;
    const int warp = tid >> 5;
    const int kb   = lane & 3;      // c: thread-in-group
    const int tb   = lane >> 2;     // g: group id (row)

    // ---- Stage 0: shifted buffer -> smem (dir-flipped) + buf output ----------
    {
        const float* bsrc = buffer + (size_t)b * CIN * LSEQ;
        const float* xsrc = x + (size_t)b * CIN;
        float* bdst = out + (size_t)B * COUT + (size_t)b * CIN * LSEQ;
        for (int idx = tid; idx < CIN * LSEQ; idx += NT) {
            int c = idx >> 5, l = idx & 31;
            float v = (l < LSEQ - 1) ? bsrc[c * LSEQ + l + 1] : xsrc[c];
            int ls = dir ? (LSEQ - 1 - l) : l;
            s_buf[c * LSEQ + ls] = v;
            if (dir == 0) bdst[idx] = v;
        }
    }
    __syncthreads();

    // ---- fc_in (f32x2): thread = (d, t-half) ---------------------------------
    {
        int d   = tid >> 1;
        int tph = tid & 1;
        u64 acc2[8];
        u64 bias = dup2(fib[d]);
#pragma unroll
        for (int p = 0; p < 8; p++) acc2[p] = bias;
        const float4* wrow = reinterpret_cast<const float4*>(fiw + d * CIN);
#pragma unroll 2
        for (int cc = 0; cc < CIN / 4; cc++) {
            float4 w4 = wrow[cc];
            u64 w0 = dup2(w4.x), w1 = dup2(w4.y), w2 = dup2(w4.z), w3 = dup2(w4.w);
            const u64* b0 = reinterpret_cast<const u64*>(s_buf + (cc * 4 + 0) * LSEQ + tph * 16);
            const u64* b1 = reinterpret_cast<const u64*>(s_buf + (cc * 4 + 1) * LSEQ + tph * 16);
            const u64* b2 = reinterpret_cast<const u64*>(s_buf + (cc * 4 + 2) * LSEQ + tph * 16);
            const u64* b3 = reinterpret_cast<const u64*>(s_buf + (cc * 4 + 3) * LSEQ + tph * 16);
#pragma unroll
            for (int p = 0; p < 8; p++) {
                acc2[p] = fma2_(b0[p], w0, acc2[p]);
                acc2[p] = fma2_(b1[p], w1, acc2[p]);
                acc2[p] = fma2_(b2[p], w2, acc2[p]);
                acc2[p] = fma2_(b3[p], w3, acc2[p]);
            }
        }
        u64* hdst = reinterpret_cast<u64*>(s_hsT + d * TST + tph * 16);
#pragma unroll
        for (int p = 0; p < 8; p++) hdst[p] = acc2[p];
    }
    __syncthreads();

    for (int l = 0; l < 2; l++) {
        const int blk = dir * 2 + l;

        // ---- block rmsnorm partials + in_proj A pack (fp16 hi only) ----------
        {
            float s = 0.f;
#pragma unroll
            for (int q = 0; q < 16; q++) {
                float v = s_hsT[(warp * 16 + q) * TST + lane];
                s += v * v;
            }
            s_red[warp * 32 + lane] = s;
        }
        {
#pragma unroll
            for (int kk = 0; kk < 2; kk++) {
                int km = warp + kk * 8;         // 0..15 = kc*2 + m
                int kc = km >> 1, m = km & 1;
#pragma unroll
                for (int r = 0; r < 4; r++) {
                    int tt = m * 16 + tb + (r & 1) * 8;
                    int k  = kc * 16 + 2 * kb + (r >> 1) * 8;
                    float v0 = s_hsT[k * TST + tt];
                    float v1 = s_hsT[(k + 1) * TST + tt];
                    s_apk[km * 128 + lane * 4 + r] = hcvt(v0, v1);
                }
            }
        }
        __syncthreads();
        if (tid < 32) {
            float s = 0.f;
#pragma unroll
            for (int w = 0; w < 8; w++) s += s_red[w * 32 + tid];
            s_inv[tid] = rsqrtf(s * (1.f / DM) + EPS);
        }
        __syncthreads();

        // ---- in_proj via fp16 tensor cores (2-pass, packed A) -----------------
        {
            const unsigned* Wf = g_ipf + (size_t)blk * (IP_NT * IP_KC * 128);
            float dacc[9][2][4];
#pragma unroll
            for (int j = 0; j < 9; j++)
#pragma unroll
                for (int m = 0; m < 2; m++)
#pragma unroll
                    for (int q = 0; q < 4; q++) dacc[j][m][q] = 0.f;

#pragma unroll 1
            for (int kc = 0; kc < IP_KC; kc++) {
                uint4 ah[2];
#pragma unroll
                for (int m = 0; m < 2; m++) {
                    int km = kc * 2 + m;
                    ah[m] = *reinterpret_cast<const uint4*>(s_apk + km * 128 + lane * 4);
                }
#pragma unroll
                for (int jg = 0; jg < 3; jg++) {
                    uint4 bf[3];
#pragma unroll
                    for (int u = 0; u < 3; u++) {
                        int n = warp + (jg * 3 + u) * 8;
                        int nn = (n < IP_NT) ? n : 0;
                        bf[u] = *reinterpret_cast<const uint4*>(
                            Wf + ((size_t)(nn * IP_KC + kc)) * 128 + lane * 4);
                    }
                    // pass 0: A x Bhi — 6 independent chains
#pragma unroll
                    for (int u = 0; u < 3; u++) {
                        int j = jg * 3 + u;
                        if (warp + j * 8 < IP_NT) {
                            mma_f16(dacc[j][0], &ah[0].x, bf[u].x, bf[u].y);
                            mma_f16(dacc[j][1], &ah[1].x, bf[u].x, bf[u].y);
                        }
                    }
                    // pass 1: A x Blo
#pragma unroll
                    for (int u = 0; u < 3; u++) {
                        int j = jg * 3 + u;
                        if (warp + j * 8 < IP_NT) {
                            mma_f16(dacc[j][0], &ah[0].x, bf[u].z, bf[u].w);
                            mma_f16(dacc[j][1], &ah[1].x, bf[u].z, bf[u].w);
                        }
                    }
                }
            }
            // epilogue: scale rows by inv[t], store to zx
#pragma unroll
            for (int j = 0; j < 9; j++) {
                int n = warp + j * 8;
                if (n < IP_NT) {
#pragma unroll
                    for (int m = 0; m < 2; m++) {
                        int t0 = m * 16 + tb;
                        float i0 = s_inv[t0], i1 = s_inv[t0 + 8];
                        int e0 = n * 8 + 2 * kb;
                        float2 v0 = make_float2(dacc[j][m][0] * i0, dacc[j][m][1] * i0);
                        float2 v1 = make_float2(dacc[j][m][2] * i1, dacc[j][m][3] * i1);
                        *reinterpret_cast<float2*>(s_zx + t0 * EPROJ + e0) = v0;
                        *reinterpret_cast<float2*>(s_zx + (t0 + 8) * EPROJ + e0) = v1;
                    }
                }
            }
        }
        __syncthreads();

        // ---- dt/dA (256 threads == 32 t * 8 heads) + conv boundary pre-reads --
        {
            int t = tid >> 3, h = tid & 7;
            float v  = s_zx[t * EPROJ + DIN + CDIM + h] + dtb[blk * NH + h];
            float sp = (v > 20.f) ? v : log1pf(__expf(v));
            s_dt[t * NH + h] = sp;
            s_dA[t * NH + h] = __expf(-__expf(alog[blk * NH + h]) * sp);
        }
        float pre[2][3];
        {
            int nb = 0;
            for (int u = tid; u < 2 * CDIM; u += NT) {
                if (u >= CDIM) {
                    float* col = s_zx + DIN + (u - CDIM);
                    pre[nb][0] = col[13 * EPROJ];
                    pre[nb][1] = col[14 * EPROJ];
                    pre[nb][2] = col[15 * EPROJ];
                    nb++;
                }
            }
        }
        __syncthreads();

        // ---- causal depthwise conv (k=4) + silu, (c, t-half) units ------------
        {
            int nb = 0;
            for (int u = tid; u < 2 * CDIM; u += NT) {
                int half = (u >= CDIM);
                int c = half ? u - CDIM : u;
                float4 w4 = *reinterpret_cast<const float4*>(cw + ((size_t)blk * CDIM + c) * 4);
                float bb  = cb[blk * CDIM + c];
                float x0, x1, x2;
                if (half) { x0 = pre[nb][0]; x1 = pre[nb][1]; x2 = pre[nb][2]; nb++; }
                else      { x0 = 0.f; x1 = 0.f; x2 = 0.f; }
                float* col = s_zx + DIN + c + (half ? 16 * EPROJ : 0);
#pragma unroll
                for (int tt = 0; tt < 16; tt++) {
                    float xc = col[tt * EPROJ];
                    float o  = fmaf(w4.x, x0, fmaf(w4.y, x1, fmaf(w4.z, x2, fmaf(w4.w, xc, bb))));
                    col[tt * EPROJ] = o * sigmoidf_(o);
                    x0 = x1; x1 = x2; x2 = xc;
                }
            }
        }
        __syncthreads();

        // ---- SSM scan (+ fused gate): thread = (head, p) ----------------------
        {
            int h = tid >> 5;
            u64 st2[NH];
#pragma unroll
            for (int n = 0; n < 8; n++) st2[n] = 0ull;
            float dskip = Dp[blk * NH + h];
            for (int t = 0; t < LSEQ; t++) {
                float* row = s_zx + t * EPROJ;
                float dAv = s_dA[t * NH + h];
                float dtv = s_dt[t * NH + h];
                float xv  = row[DIN + tid];
                u64 dA2  = dup2(dAv);
                u64 dtx2 = dup2(dtv * xv);
                const ulonglong2* Bp = reinterpret_cast<const ulonglong2*>(row + 2 * DIN);
                const ulonglong2* Cp = reinterpret_cast<const ulonglong2*>(row + 2 * DIN + DST);
                u64 y2 = 0ull;
#pragma unroll
                for (int q = 0; q < 4; q++) {
                    ulonglong2 b2 = Bp[q];
                    ulonglong2 c2 = Cp[q];
                    st2[2*q]   = fma2_(st2[2*q],   dA2, mul2_(dtx2, b2.x));
                    y2         = fma2_(st2[2*q],   c2.x, y2);
                    st2[2*q+1] = fma2_(st2[2*q+1], dA2, mul2_(dtx2, b2.y));
                    y2         = fma2_(st2[2*q+1], c2.y, y2);
                }
                float ylo, yhi;
                upk2(y2, ylo, yhi);
                float yv = fmaf(dskip, xv, ylo + yhi);
                float z  = row[tid];
                row[DIN + tid] = yv * z * sigmoidf_(z);   // fused gate
            }
        }
        __syncthreads();

        // ---- mixer rmsnorm partials + out_proj A pack (fp16 hi, z cols dead) ---
        {
            int t = tid >> 3, part = tid & 7;
            const float4* gp = reinterpret_cast<const float4*>(s_zx + t * EPROJ + DIN + part * 32);
            float s = 0.f;
#pragma unroll
            for (int q = 0; q < 8; q++) {
                float4 v = gp[q];
                s += v.x * v.x + v.y * v.y + v.z * v.z + v.w * v.w;
            }
            s += __shfl_xor_sync(0xffffffffu, s, 1);
            s += __shfl_xor_sync(0xffffffffu, s, 2);
            s += __shfl_xor_sync(0xffffffffu, s, 4);
            if (part == 0) s_inv2[t] = rsqrtf(s * (1.f / DIN) + EPS);
        }
        {
#pragma unroll
            for (int kk = 0; kk < 4; kk++) {
                int km = warp + kk * 8;         // 0..31 = kc*2 + m
                int kc = km >> 1, m = km & 1;
#pragma unroll
                for (int r = 0; r < 4; r++) {
                    int tt = m * 16 + tb + (r & 1) * 8;
                    int e  = DIN + kc * 16 + 2 * kb + (r >> 1) * 8;
                    float2 v = *reinterpret_cast<const float2*>(s_zx + tt * EPROJ + e);
                    int w = km * 128 + lane * 4 + r;
                    s_zxw[ZIDX(w)] = hcvt(v.x, v.y);
                }
            }
        }
        __syncthreads();

        // ---- out_proj via fp16 tensor cores (2-pass, packed A) + residual -----
        {
            const unsigned* Wf = g_opf + (size_t)blk * (OP_NT * OP_KC * 128);
            float dacc[2][2][4];
#pragma unroll
            for (int j = 0; j < 2; j++)
#pragma unroll
                for (int m = 0; m < 2; m++)
#pragma unroll
                    for (int q = 0; q < 4; q++) dacc[j][m][q] = 0.f;

#pragma unroll 1
            for (int kc = 0; kc < OP_KC; kc++) {
                uint4 ah[2];
#pragma unroll
                for (int m = 0; m < 2; m++) {
                    int w0 = (kc * 2 + m) * 128 + lane * 4;
                    ah[m] = *reinterpret_cast<const uint4*>(s_zxw + ZIDX(w0));
                }
                uint4 bf0 = *reinterpret_cast<const uint4*>(
                    Wf + ((size_t)((warp + 0) * OP_KC + kc)) * 128 + lane * 4);
                uint4 bf1 = *reinterpret_cast<const uint4*>(
                    Wf + ((size_t)((warp + 8) * OP_KC + kc)) * 128 + lane * 4);
                // pass 0: A x Bhi — 4 chains
                mma_f16(dacc[0][0], &ah[0].x, bf0.x, bf0.y);
                mma_f16(dacc[0][1], &ah[1].x, bf0.x, bf0.y);
                mma_f16(dacc[1][0], &ah[0].x, bf1.x, bf1.y);
                mma_f16(dacc[1][1], &ah[1].x, bf1.x, bf1.y);
                // pass 1: A x Blo
                mma_f16(dacc[0][0], &ah[0].x, bf0.z, bf0.w);
                mma_f16(dacc[0][1], &ah[1].x, bf0.z, bf0.w);
                mma_f16(dacc[1][0], &ah[0].x, bf1.z, bf1.w);
                mma_f16(dacc[1][1], &ah[1].x, bf1.z, bf1.w);
            }
            // epilogue: hsT[d][t] += inv2[t] * D[t][d]
#pragma unroll
            for (int j = 0; j < 2; j++) {
                int n = warp + j * 8;
#pragma unroll
                for (int m = 0; m < 2; m++) {
                    int t0 = m * 16 + tb;
                    float i0 = s_inv2[t0], i1 = s_inv2[t0 + 8];
                    int d0 = n * 8 + 2 * kb;
                    s_hsT[d0 * TST + t0]           += dacc[j][m][0] * i0;
                    s_hsT[(d0 + 1) * TST + t0]     += dacc[j][m][1] * i0;
                    s_hsT[d0 * TST + t0 + 8]       += dacc[j][m][2] * i1;
                    s_hsT[(d0 + 1) * TST + t0 + 8] += dacc[j][m][3] * i1;
                }
            }
        }
        __syncthreads();
    } // layer

    // ---- final rmsnorm(norm_f) over d ------------------------------------------
    {
        float s = 0.f;
#pragma unroll
        for (int q = 0; q < 16; q++) {
            float v = s_hsT[(warp * 16 + q) * TST + lane];
            s += v * v;
        }
        s_red[warp * 32 + lane] = s;
    }
    __syncthreads();
    if (tid < 32) {
        float s = 0.f;
#pragma unroll
        for (int w = 0; w < 8; w++) s += s_red[w * 32 + tid];
        s_inv[tid] = rsqrtf(s * (1.f / DM) + EPS);
    }
    __syncthreads();

    // ---- L-weighted accumulate -> g_A ------------------------------------------
    if (tid < DM) {
        const float* hrow = s_hsT + tid * TST;
        float s = 0.f;
#pragma unroll
        for (int t = 0; t < LSEQ; t++) {
            float wl = olw[dir ? (LSEQ - 1 - t) : t];
            s = fmaf(wl * s_inv[t], hrow[t], s);
        }
        g_A[((size_t)b * 2 + dir) * DM + tid] = s * nfw[dir * DM + tid];
    }
}

extern "C" void kernel_launch(void* const* d_in, const int* in_sizes, int n_in,
                              void* d_out, int out_size) {
    const float* x      = (const float*)d_in[0];
    const float* buffer = (const float*)d_in[1];
    const float* fiw    = (const float*)d_in[2];
    const float* fib    = (const float*)d_in[3];
    const float* bnw    = (const float*)d_in[4];
    const float* ipw    = (const float*)d_in[5];
    const float* cw     = (const float*)d_in[6];
    const float* cb     = (const float*)d_in[7];
    const float* dtb    = (const float*)d_in[8];
    const float* alog   = (const float*)d_in[9];
    const float* Dp     = (const float*)d_in[10];
    const float* mnw    = (const float*)d_in[11];
    const float* opw    = (const float*)d_in[12];
    const float* nfw    = (const float*)d_in[13];
    const float* fow    = (const float*)d_in[14];
    const float* fob    = (const float*)d_in[15];
    const float* olw    = (const float*)d_in[16];
    const float* olb    = (const float*)d_in[17];
    float* out = (float*)d_out;

    int B = in_sizes[0] / CIN;   // 1024
    size_t smem_bytes = (size_t)SMEM_FLOATS * sizeof(float);

    cudaFuncSetAttribute(mamba_actor_kernel,
                         cudaFuncAttributeMaxDynamicSharedMemorySize,
                         (int)smem_bytes);

    int prep_total = IPF_N + OPF_N;
    prep_weights<<<(prep_total + 255) / 256, 256>>>(ipw, bnw, opw, mnw);

    mamba_actor_kernel<<<2 * B, NT, smem_bytes>>>(
        x, buffer, fiw, fib, cw, cb, dtb, alog,
        Dp, nfw, olw, out);

    finalize_kernel<<<(B * COUT + 255) / 256, 256>>>(fow, fob, olw, olb, out, B);
}

// round 15
// speedup vs baseline: 1.2813x; 1.1082x over previous
#include <cuda_runtime.h>
#include <cuda_fp16.h>
#include <math.h>

#define EPS      1e-5f
#define LSEQ     32
#define DM       128
#define CIN      96
#define COUT     12
#define DIN      256
#define DST      16
#define NH       8
#define CDIM     288          // DIN + 2*DST
#define EPROJ    552          // semantic in_proj cols
#define ESTR     584          // zx row stride (padded for 72 n-tiles)
#define TST      36           // hs transposed stride
#define NT       256
#define MAXB     1024

#define IP_NT    72           // in_proj n-tiles (padded from 69)
#define IP_KC    8            // in_proj k16-chunks (128/16)
#define OP_NT    16           // out_proj n-tiles (128/8)
#define OP_KC    16           // out_proj k16-chunks (256/16)
#define FI_KC    6            // fc_in k16-chunks (96/16)

typedef unsigned long long u64;

// device scratch: fp16 hi/lo fragment-packed weights (one 32-bit word = f16x2)
#define IPF_N (4 * IP_NT * IP_KC * 128)   // 294912 words
#define OPF_N (4 * OP_NT * OP_KC * 128)   // 131072 words
#define FIF_N (16 * FI_KC * 128)          // 12288 words
__device__ unsigned g_ipf[IPF_N];
__device__ unsigned g_opf[OPF_N];
__device__ unsigned g_fif[FIF_N];
__device__ float g_A[(size_t)MAXB * 2 * DM];

// shared memory layout (floats)
#define OFF_APK   0                          // 4096: s_buf (stage0) / in_proj A-pack
#define OFF_HST   4096                       // 128*36 = 4608
#define OFF_ZX    (OFF_HST + DM*TST)         // 32*584 = 18688
#define OFF_DT    (OFF_ZX + LSEQ*ESTR)       // 256
#define OFF_DA    (OFF_DT + LSEQ*NH)         // 256
#define OFF_INV   (OFF_DA + LSEQ*NH)         // 32
#define OFF_INV2  (OFF_INV + LSEQ)           // 32
#define OFF_RED   (OFF_INV2 + LSEQ)          // 256
#define SMEM_FLOATS (OFF_RED + NT)           // 28224 floats = 112896 B

// packed A words in dead z-columns of s_zx: word w -> row w>>8, col w&255
#define ZIDX(w) ((((w) >> 8) * ESTR) + ((w) & 255))

__device__ __forceinline__ float sigmoidf_(float v) {
    return 1.f / (1.f + __expf(-v));
}
__device__ __forceinline__ u64 pk2(float lo, float hi) {
    u64 r; asm("mov.b64 %0,{%1,%2};" : "=l"(r) : "f"(lo), "f"(hi)); return r;
}
__device__ __forceinline__ u64 dup2(float v) { return pk2(v, v); }
__device__ __forceinline__ void upk2(u64 a, float& lo, float& hi) {
    asm("mov.b64 {%0,%1},%2;" : "=f"(lo), "=f"(hi) : "l"(a));
}
__device__ __forceinline__ u64 fma2_(u64 a, u64 b, u64 c) {
    u64 d; asm("fma.rn.f32x2 %0,%1,%2,%3;" : "=l"(d) : "l"(a), "l"(b), "l"(c)); return d;
}
__device__ __forceinline__ u64 mul2_(u64 a, u64 b) {
    u64 d; asm("mul.rn.f32x2 %0,%1,%2;" : "=l"(d) : "l"(a), "l"(b)); return d;
}

// convert (v0, v1) -> packed f16x2 (v0 in low half, matching MMA fragment order)
__device__ __forceinline__ unsigned hcvt(float v0, float v1) {
    unsigned r;
    asm("cvt.rn.f16x2.f32 %0,%1,%2;" : "=r"(r) : "f"(v1), "f"(v0));
    return r;
}
// split (v0, v1) -> fp16 hi (rn) and lo (rn of residual)
__device__ __forceinline__ void hsplit(float v0, float v1, unsigned& hi, unsigned& lo) {
    hi = hcvt(v0, v1);
    __half2 h = *reinterpret_cast<__half2*>(&hi);
    float h0 = __low2float(h), h1 = __high2float(h);
    lo = hcvt(v0 - h0, v1 - h1);
}
__device__ __forceinline__ void mma_f16(float* d, const unsigned* a,
                                        unsigned b0, unsigned b1) {
    asm volatile(
        "mma.sync.aligned.m16n8k16.row.col.f32.f16.f16.f32 "
        "{%0,%1,%2,%3},{%4,%5,%6,%7},{%8,%9},{%0,%1,%2,%3};"
        : "+f"(d[0]), "+f"(d[1]), "+f"(d[2]), "+f"(d[3])
        : "r"(a[0]), "r"(a[1]), "r"(a[2]), "r"(a[3]), "r"(b0), "r"(b1));
}

// ---- prep: fold norms, fp16 hi/lo split, B-fragment lane order --------------
__global__ void prep_weights(const float* __restrict__ ipw,
                             const float* __restrict__ bnw,
                             const float* __restrict__ opw,
                             const float* __restrict__ mnw,
                             const float* __restrict__ fiw) {
    int i = blockIdx.x * blockDim.x + threadIdx.x;
    if (i < IPF_N) {
        int blk = i / (IP_NT * IP_KC * 128);
        int r   = i - blk * (IP_NT * IP_KC * 128);
        int n   = r / (IP_KC * 128);
        int q   = r - n * (IP_KC * 128);
        int kc  = q >> 7;
        int rem = q & 127;
        int lane = rem >> 2, comp = rem & 3;
        int g = lane >> 2, c = lane & 3;
        int e  = n * 8 + g;
        int k0 = kc * 16 + 2 * c + ((comp & 1) ? 8 : 0);
        float v0 = 0.f, v1 = 0.f;
        if (e < EPROJ) {
            v0 = ipw[((size_t)blk * EPROJ + e) * DM + k0]     * bnw[blk * DM + k0];
            v1 = ipw[((size_t)blk * EPROJ + e) * DM + k0 + 1] * bnw[blk * DM + k0 + 1];
        }
        unsigned hi, lo;
        hsplit(v0, v1, hi, lo);
        g_ipf[i] = (comp < 2) ? hi : lo;
    } else if (i < IPF_N + OPF_N) {
        int j   = i - IPF_N;
        int blk = j >> 15;
        int r   = j & 32767;
        int n   = r >> 11;
        int q   = r & 2047;
        int kc  = q >> 7;
        int rem = q & 127;
        int lane = rem >> 2, comp = rem & 3;
        int g = lane >> 2, c = lane & 3;
        int d  = n * 8 + g;
        int e0 = kc * 16 + 2 * c + ((comp & 1) ? 8 : 0);
        float v0 = opw[((size_t)blk * DM + d) * DIN + e0]     * mnw[blk * DIN + e0];
        float v1 = opw[((size_t)blk * DM + d) * DIN + e0 + 1] * mnw[blk * DIN + e0 + 1];
        unsigned hi, lo;
        hsplit(v0, v1, hi, lo);
        g_opf[j] = (comp < 2) ? hi : lo;
    } else if (i < IPF_N + OPF_N + FIF_N) {
        int j   = i - IPF_N - OPF_N;
        int n   = j / (FI_KC * 128);
        int q   = j - n * (FI_KC * 128);
        int kc  = q >> 7;
        int rem = q & 127;
        int lane = rem >> 2, comp = rem & 3;
        int g = lane >> 2, c = lane & 3;
        int d  = n * 8 + g;
        int k0 = kc * 16 + 2 * c + ((comp & 1) ? 8 : 0);
        float v0 = fiw[d * CIN + k0];
        float v1 = fiw[d * CIN + k0 + 1];
        unsigned hi, lo;
        hsplit(v0, v1, hi, lo);
        g_fif[j] = (comp < 2) ? hi : lo;
    }
}

// ---- finalize ----------------------------------------------------------------
__global__ void finalize_kernel(const float* __restrict__ fow,
                                const float* __restrict__ fob,
                                const float* __restrict__ olw,
                                const float* __restrict__ olb,
                                float* __restrict__ out, int B) {
    int idx = blockIdx.x * blockDim.x + threadIdx.x;
    if (idx >= B * COUT) return;
    int b = idx / COUT, o = idx - b * COUT;
    float Swl = 0.f;
#pragma unroll
    for (int t = 0; t < LSEQ; t++) Swl += olw[t];
    const float* A0 = g_A + (size_t)b * 2 * DM;
    float acc = 0.f;
#pragma unroll 4
    for (int d = 0; d < DM; d++) acc = fmaf(fow[o * DM + d], A0[d] + A0[DM + d], acc);
    out[idx] = acc + fob[o] * Swl + olb[0];
}

// ---- main: one CTA per (batch, direction) -------------------------------------
__global__ void __launch_bounds__(NT, 2) mamba_actor_kernel(
    const float* __restrict__ x,        // (B, 96)
    const float* __restrict__ buffer,   // (B, 96, 32)
    const float* __restrict__ fib,      // (128,)
    const float* __restrict__ cw,       // (4, 288, 4)
    const float* __restrict__ cb,       // (4, 288)
    const float* __restrict__ dtb,      // (4, 8)
    const float* __restrict__ alog,     // (4, 8)
    const float* __restrict__ Dp,       // (4, 8)
    const float* __restrict__ nfw,      // (2, 128)
    const float* __restrict__ olw,      // (1, 32)
    float* __restrict__ out)
{
    extern __shared__ float sm[];
    float*    s_buf  = sm + OFF_APK;   // stage0/fc_in only
    unsigned* s_apk  = reinterpret_cast<unsigned*>(sm + OFF_APK);
    float*    s_hsT  = sm + OFF_HST;   // [k][t], stride TST
    float*    s_zx   = sm + OFF_ZX;    // [t][e], stride ESTR
    unsigned* s_zxw  = reinterpret_cast<unsigned*>(sm + OFF_ZX);
    float*    s_dt   = sm + OFF_DT;
    float*    s_dA   = sm + OFF_DA;
    float*    s_inv  = sm + OFF_INV;
    float*    s_inv2 = sm + OFF_INV2;
    float*    s_red  = sm + OFF_RED;

    const int B    = gridDim.x >> 1;
    const int b    = blockIdx.x >> 1;
    const int dir  = blockIdx.x & 1;
    const int tid  = threadIdx.x;
    const int lane = tid & 31;
    const int warp = tid >> 5;
    const int kb   = lane & 3;      // c: thread-in-group
    const int tb   = lane >> 2;     // g: group id (row)

    // ---- Stage 0: shifted buffer -> smem (dir-flipped, [c][t]) + buf output --
    {
        const float* bsrc = buffer + (size_t)b * CIN * LSEQ;
        const float* xsrc = x + (size_t)b * CIN;
        float* bdst = out + (size_t)B * COUT + (size_t)b * CIN * LSEQ;
        for (int idx = tid; idx < CIN * LSEQ; idx += NT) {
            int c = idx >> 5, l = idx & 31;
            float v = (l < LSEQ - 1) ? bsrc[c * LSEQ + l + 1] : xsrc[c];
            int ls = dir ? (LSEQ - 1 - l) : l;
            s_buf[c * LSEQ + ls] = v;
            if (dir == 0) bdst[idx] = v;
        }
    }
    __syncthreads();

    // ---- fc_in A pack: buf fragments -> fp16 into s_zxw (free scratch) -------
    {
        // km = kc*2 + m, 12 fragments. warps 0..7 take km=warp; warps 0..3 also km=8+warp
#pragma unroll
        for (int kk = 0; kk < 2; kk++) {
            int km = (kk == 0) ? warp : (8 + warp);
            if (kk == 0 || warp < 4) {
                int kc = km >> 1, m = km & 1;
#pragma unroll
                for (int r = 0; r < 4; r++) {
                    int tt = m * 16 + tb + (r & 1) * 8;
                    int k  = kc * 16 + 2 * kb + (r >> 1) * 8;
                    float v0 = s_buf[k * LSEQ + tt];
                    float v1 = s_buf[(k + 1) * LSEQ + tt];
                    s_zxw[km * 128 + lane * 4 + r] = hcvt(v0, v1);
                }
            }
        }
    }
    __syncthreads();

    // ---- fc_in via fp16 tensor cores (2-pass): hsT[d][t] = buf . fiw^T + fib -
    {
        float dacc[2][2][4];
#pragma unroll
        for (int j = 0; j < 2; j++)
#pragma unroll
            for (int m = 0; m < 2; m++)
#pragma unroll
                for (int q = 0; q < 4; q++) dacc[j][m][q] = 0.f;
#pragma unroll
        for (int kc = 0; kc < FI_KC; kc++) {
            uint4 ah[2];
#pragma unroll
            for (int m = 0; m < 2; m++)
                ah[m] = *reinterpret_cast<const uint4*>(s_zxw + (kc * 2 + m) * 128 + lane * 4);
            uint4 bf0 = *reinterpret_cast<const uint4*>(
                g_fif + ((size_t)((warp * 2 + 0) * FI_KC + kc)) * 128 + lane * 4);
            uint4 bf1 = *reinterpret_cast<const uint4*>(
                g_fif + ((size_t)((warp * 2 + 1) * FI_KC + kc)) * 128 + lane * 4);
            mma_f16(dacc[0][0], &ah[0].x, bf0.x, bf0.y);
            mma_f16(dacc[0][1], &ah[1].x, bf0.x, bf0.y);
            mma_f16(dacc[1][0], &ah[0].x, bf1.x, bf1.y);
            mma_f16(dacc[1][1], &ah[1].x, bf1.x, bf1.y);
            mma_f16(dacc[0][0], &ah[0].x, bf0.z, bf0.w);
            mma_f16(dacc[0][1], &ah[1].x, bf0.z, bf0.w);
            mma_f16(dacc[1][0], &ah[0].x, bf1.z, bf1.w);
            mma_f16(dacc[1][1], &ah[1].x, bf1.z, bf1.w);
        }
#pragma unroll
        for (int j = 0; j < 2; j++) {
            int d0 = (warp * 2 + j) * 8 + 2 * kb;
            float f0 = fib[d0], f1 = fib[d0 + 1];
#pragma unroll
            for (int m = 0; m < 2; m++) {
                int t0 = m * 16 + tb;
                s_hsT[d0 * TST + t0]           = dacc[j][m][0] + f0;
                s_hsT[(d0 + 1) * TST + t0]     = dacc[j][m][1] + f1;
                s_hsT[d0 * TST + t0 + 8]       = dacc[j][m][2] + f0;
                s_hsT[(d0 + 1) * TST + t0 + 8] = dacc[j][m][3] + f1;
            }
        }
    }
    __syncthreads();

    for (int l = 0; l < 2; l++) {
        const int blk = dir * 2 + l;

        // ---- block rmsnorm partials + in_proj A pack (fp16 hi only) ----------
        {
            float s = 0.f;
#pragma unroll
            for (int q = 0; q < 16; q++) {
                float v = s_hsT[(warp * 16 + q) * TST + lane];
                s += v * v;
            }
            s_red[warp * 32 + lane] = s;
        }
        {
#pragma unroll
            for (int kk = 0; kk < 2; kk++) {
                int km = warp + kk * 8;         // 0..15 = kc*2 + m
                int kc = km >> 1, m = km & 1;
#pragma unroll
                for (int r = 0; r < 4; r++) {
                    int tt = m * 16 + tb + (r & 1) * 8;
                    int k  = kc * 16 + 2 * kb + (r >> 1) * 8;
                    float v0 = s_hsT[k * TST + tt];
                    float v1 = s_hsT[(k + 1) * TST + tt];
                    s_apk[km * 128 + lane * 4 + r] = hcvt(v0, v1);
                }
            }
        }
        __syncthreads();
        if (tid < 32) {
            float s = 0.f;
#pragma unroll
            for (int w = 0; w < 8; w++) s += s_red[w * 32 + tid];
            s_inv[tid] = rsqrtf(s * (1.f / DM) + EPS);
        }
        __syncthreads();

        // ---- in_proj via fp16 tensor cores (2-pass, packed A, 72 tiles) -------
        {
            const unsigned* Wf = g_ipf + (size_t)blk * (IP_NT * IP_KC * 128);
            float dacc[9][2][4];
#pragma unroll
            for (int j = 0; j < 9; j++)
#pragma unroll
                for (int m = 0; m < 2; m++)
#pragma unroll
                    for (int q = 0; q < 4; q++) dacc[j][m][q] = 0.f;

#pragma unroll 1
            for (int kc = 0; kc < IP_KC; kc++) {
                uint4 ah[2];
#pragma unroll
                for (int m = 0; m < 2; m++) {
                    int km = kc * 2 + m;
                    ah[m] = *reinterpret_cast<const uint4*>(s_apk + km * 128 + lane * 4);
                }
#pragma unroll
                for (int jg = 0; jg < 3; jg++) {
                    uint4 bf[3];
#pragma unroll
                    for (int u = 0; u < 3; u++) {
                        int n = warp + (jg * 3 + u) * 8;
                        bf[u] = *reinterpret_cast<const uint4*>(
                            Wf + ((size_t)(n * IP_KC + kc)) * 128 + lane * 4);
                    }
#pragma unroll
                    for (int u = 0; u < 3; u++) {
                        int j = jg * 3 + u;
                        mma_f16(dacc[j][0], &ah[0].x, bf[u].x, bf[u].y);
                        mma_f16(dacc[j][1], &ah[1].x, bf[u].x, bf[u].y);
                    }
#pragma unroll
                    for (int u = 0; u < 3; u++) {
                        int j = jg * 3 + u;
                        mma_f16(dacc[j][0], &ah[0].x, bf[u].z, bf[u].w);
                        mma_f16(dacc[j][1], &ah[1].x, bf[u].z, bf[u].w);
                    }
                }
            }
            // epilogue: scale rows by inv[t], store to zx
#pragma unroll
            for (int j = 0; j < 9; j++) {
                int n = warp + j * 8;
#pragma unroll
                for (int m = 0; m < 2; m++) {
                    int t0 = m * 16 + tb;
                    float i0 = s_inv[t0], i1 = s_inv[t0 + 8];
                    int e0 = n * 8 + 2 * kb;
                    float2 v0 = make_float2(dacc[j][m][0] * i0, dacc[j][m][1] * i0);
                    float2 v1 = make_float2(dacc[j][m][2] * i1, dacc[j][m][3] * i1);
                    *reinterpret_cast<float2*>(s_zx + t0 * ESTR + e0) = v0;
                    *reinterpret_cast<float2*>(s_zx + (t0 + 8) * ESTR + e0) = v1;
                }
            }
        }
        __syncthreads();

        // ---- dt/dA (256 threads == 32 t * 8 heads) + conv boundary pre-reads --
        {
            int t = tid >> 3, h = tid & 7;
            float v  = s_zx[t * ESTR + DIN + CDIM + h] + dtb[blk * NH + h];
            float sp = (v > 20.f) ? v : log1pf(__expf(v));
            s_dt[t * NH + h] = sp;
            s_dA[t * NH + h] = __expf(-__expf(alog[blk * NH + h]) * sp);
        }
        float pre[2][3];
        {
            int nb = 0;
            for (int u = tid; u < 2 * CDIM; u += NT) {
                if (u >= CDIM) {
                    float* col = s_zx + DIN + (u - CDIM);
                    pre[nb][0] = col[13 * ESTR];
                    pre[nb][1] = col[14 * ESTR];
                    pre[nb][2] = col[15 * ESTR];
                    nb++;
                }
            }
        }
        __syncthreads();

        // ---- causal depthwise conv (k=4) + silu, (c, t-half) units ------------
        {
            int nb = 0;
            for (int u = tid; u < 2 * CDIM; u += NT) {
                int half = (u >= CDIM);
                int c = half ? u - CDIM : u;
                float4 w4 = *reinterpret_cast<const float4*>(cw + ((size_t)blk * CDIM + c) * 4);
                float bb  = cb[blk * CDIM + c];
                float x0, x1, x2;
                if (half) { x0 = pre[nb][0]; x1 = pre[nb][1]; x2 = pre[nb][2]; nb++; }
                else      { x0 = 0.f; x1 = 0.f; x2 = 0.f; }
                float* col = s_zx + DIN + c + (half ? 16 * ESTR : 0);
#pragma unroll
                for (int tt = 0; tt < 16; tt++) {
                    float xc = col[tt * ESTR];
                    float o  = fmaf(w4.x, x0, fmaf(w4.y, x1, fmaf(w4.z, x2, fmaf(w4.w, xc, bb))));
                    col[tt * ESTR] = o * sigmoidf_(o);
                    x0 = x1; x1 = x2; x2 = xc;
                }
            }
        }
        __syncthreads();

        // ---- SSM scan (+ fused gate): thread = (head, p) ----------------------
        {
            int h = tid >> 5;
            u64 st2[NH];
#pragma unroll
            for (int n = 0; n < 8; n++) st2[n] = 0ull;
            float dskip = Dp[blk * NH + h];
            for (int t = 0; t < LSEQ; t++) {
                float* row = s_zx + t * ESTR;
                float dAv = s_dA[t * NH + h];
                float dtv = s_dt[t * NH + h];
                float xv  = row[DIN + tid];
                u64 dA2  = dup2(dAv);
                u64 dtx2 = dup2(dtv * xv);
                const ulonglong2* Bp = reinterpret_cast<const ulonglong2*>(row + 2 * DIN);
                const ulonglong2* Cp = reinterpret_cast<const ulonglong2*>(row + 2 * DIN + DST);
                u64 y2 = 0ull;
#pragma unroll
                for (int q = 0; q < 4; q++) {
                    ulonglong2 b2 = Bp[q];
                    ulonglong2 c2 = Cp[q];
                    st2[2*q]   = fma2_(st2[2*q],   dA2, mul2_(dtx2, b2.x));
                    y2         = fma2_(st2[2*q],   c2.x, y2);
                    st2[2*q+1] = fma2_(st2[2*q+1], dA2, mul2_(dtx2, b2.y));
                    y2         = fma2_(st2[2*q+1], c2.y, y2);
                }
                float ylo, yhi;
                upk2(y2, ylo, yhi);
                float yv = fmaf(dskip, xv, ylo + yhi);
                float z  = row[tid];
                row[DIN + tid] = yv * z * sigmoidf_(z);   // fused gate
            }
        }
        __syncthreads();

        // ---- mixer rmsnorm partials + out_proj A pack (fp16 hi, z cols dead) ---
        {
            int t = tid >> 3, part = tid & 7;
            const float4* gp = reinterpret_cast<const float4*>(s_zx + t * ESTR + DIN + part * 32);
            float s = 0.f;
#pragma unroll
            for (int q = 0; q < 8; q++) {
                float4 v = gp[q];
                s += v.x * v.x + v.y * v.y + v.z * v.z + v.w * v.w;
            }
            s += __shfl_xor_sync(0xffffffffu, s, 1);
            s += __shfl_xor_sync(0xffffffffu, s, 2);
            s += __shfl_xor_sync(0xffffffffu, s, 4);
            if (part == 0) s_inv2[t] = rsqrtf(s * (1.f / DIN) + EPS);
        }
        {
#pragma unroll
            for (int kk = 0; kk < 4; kk++) {
                int km = warp + kk * 8;         // 0..31 = kc*2 + m
                int kc = km >> 1, m = km & 1;
#pragma unroll
                for (int r = 0; r < 4; r++) {
                    int tt = m * 16 + tb + (r & 1) * 8;
                    int e  = DIN + kc * 16 + 2 * kb + (r >> 1) * 8;
                    float2 v = *reinterpret_cast<const float2*>(s_zx + tt * ESTR + e);
                    int w = km * 128 + lane * 4 + r;
                    s_zxw[ZIDX(w)] = hcvt(v.x, v.y);
                }
            }
        }
        __syncthreads();

        // ---- out_proj via fp16 tensor cores (2-pass, packed A) + residual -----
        {
            const unsigned* Wf = g_opf + (size_t)blk * (OP_NT * OP_KC * 128);
            float dacc[2][2][4];
#pragma unroll
            for (int j = 0; j < 2; j++)
#pragma unroll
                for (int m = 0; m < 2; m++)
#pragma unroll
                    for (int q = 0; q < 4; q++) dacc[j][m][q] = 0.f;

#pragma unroll 1
            for (int kc = 0; kc < OP_KC; kc++) {
                uint4 ah[2];
#pragma unroll
                for (int m = 0; m < 2; m++) {
                    int w0 = (kc * 2 + m) * 128 + lane * 4;
                    ah[m] = *reinterpret_cast<const uint4*>(s_zxw + ZIDX(w0));
                }
                uint4 bf0 = *reinterpret_cast<const uint4*>(
                    Wf + ((size_t)((warp + 0) * OP_KC + kc)) * 128 + lane * 4);
                uint4 bf1 = *reinterpret_cast<const uint4*>(
                    Wf + ((size_t)((warp + 8) * OP_KC + kc)) * 128 + lane * 4);
                mma_f16(dacc[0][0], &ah[0].x, bf0.x, bf0.y);
                mma_f16(dacc[0][1], &ah[1].x, bf0.x, bf0.y);
                mma_f16(dacc[1][0], &ah[0].x, bf1.x, bf1.y);
                mma_f16(dacc[1][1], &ah[1].x, bf1.x, bf1.y);
                mma_f16(dacc[0][0], &ah[0].x, bf0.z, bf0.w);
                mma_f16(dacc[0][1], &ah[1].x, bf0.z, bf0.w);
                mma_f16(dacc[1][0], &ah[0].x, bf1.z, bf1.w);
                mma_f16(dacc[1][1], &ah[1].x, bf1.z, bf1.w);
            }
            // epilogue: hsT[d][t] += inv2[t] * D[t][d]
#pragma unroll
            for (int j = 0; j < 2; j++) {
                int n = warp + j * 8;
#pragma unroll
                for (int m = 0; m < 2; m++) {
                    int t0 = m * 16 + tb;
                    float i0 = s_inv2[t0], i1 = s_inv2[t0 + 8];
                    int d0 = n * 8 + 2 * kb;
                    s_hsT[d0 * TST + t0]           += dacc[j][m][0] * i0;
                    s_hsT[(d0 + 1) * TST + t0]     += dacc[j][m][1] * i0;
                    s_hsT[d0 * TST + t0 + 8]       += dacc[j][m][2] * i1;
                    s_hsT[(d0 + 1) * TST + t0 + 8] += dacc[j][m][3] * i1;
                }
            }
        }
        __syncthreads();
    } // layer

    // ---- final rmsnorm(norm_f) over d ------------------------------------------
    {
        float s = 0.f;
#pragma unroll
        for (int q = 0; q < 16; q++) {
            float v = s_hsT[(warp * 16 + q) * TST + lane];
            s += v * v;
        }
        s_red[warp * 32 + lane] = s;
    }
    __syncthreads();
    if (tid < 32) {
        float s = 0.f;
#pragma unroll
        for (int w = 0; w < 8; w++) s += s_red[w * 32 + tid];
        s_inv[tid] = rsqrtf(s * (1.f / DM) + EPS);
    }
    __syncthreads();

    // ---- L-weighted accumulate -> g_A ------------------------------------------
    if (tid < DM) {
        const float* hrow = s_hsT + tid * TST;
        float s = 0.f;
#pragma unroll
        for (int t = 0; t < LSEQ; t++) {
            float wl = olw[dir ? (LSEQ - 1 - t) : t];
            s = fmaf(wl * s_inv[t], hrow[t], s);
        }
        g_A[((size_t)b * 2 + dir) * DM + tid] = s * nfw[dir * DM + tid];
    }
}

extern "C" void kernel_launch(void* const* d_in, const int* in_sizes, int n_in,
                              void* d_out, int out_size) {
    const float* x      = (const float*)d_in[0];
    const float* buffer = (const float*)d_in[1];
    const float* fiw    = (const float*)d_in[2];
    const float* fib    = (const float*)d_in[3];
    const float* bnw    = (const float*)d_in[4];
    const float* ipw    = (const float*)d_in[5];
    const float* cw     = (const float*)d_in[6];
    const float* cb     = (const float*)d_in[7];
    const float* dtb    = (const float*)d_in[8];
    const float* alog   = (const float*)d_in[9];
    const float* Dp     = (const float*)d_in[10];
    const float* mnw    = (const float*)d_in[11];
    const float* opw    = (const float*)d_in[12];
    const float* nfw    = (const float*)d_in[13];
    const float* fow    = (const float*)d_in[14];
    const float* fob    = (const float*)d_in[15];
    const float* olw    = (const float*)d_in[16];
    const float* olb    = (const float*)d_in[17];
    float* out = (float*)d_out;

    int B = in_sizes[0] / CIN;   // 1024
    size_t smem_bytes = (size_t)SMEM_FLOATS * sizeof(float);

    cudaFuncSetAttribute(mamba_actor_kernel,
                         cudaFuncAttributeMaxDynamicSharedMemorySize,
                         (int)smem_bytes);

    int prep_total = IPF_N + OPF_N + FIF_N;
    prep_weights<<<(prep_total + 255) / 256, 256>>>(ipw, bnw, opw, mnw, fiw);

    mamba_actor_kernel<<<2 * B, NT, smem_bytes>>>(
        x, buffer, fib, cw, cb, dtb, alog,
        Dp, nfw, olw, out);

    finalize_kernel<<<(B * COUT + 255) / 256, 256>>>(fow, fob, olw, olb, out, B);
}

// round 16
// speedup vs baseline: 1.3081x; 1.0209x over previous
#include <cuda_runtime.h>
#include <cuda_fp16.h>
#include <math.h>

#define EPS      1e-5f
#define LSEQ     32
#define DM       128
#define CIN      96
#define COUT     12
#define DIN      256
#define DST      16
#define NH       8
#define CDIM     288          // DIN + 2*DST
#define EPROJ    552          // semantic in_proj cols
#define ESTR     584          // zx row stride (padded for 72 n-tiles)
#define TST      36           // hs transposed stride
#define NT       256
#define MAXB     1024

#define IP_NT    72           // in_proj n-tiles (padded from 69)
#define IP_KC    8            // in_proj k16-chunks (128/16)
#define OP_NT    16           // out_proj n-tiles (128/8)
#define OP_KC    16           // out_proj k16-chunks (256/16)
#define FI_KC    6            // fc_in k16-chunks (96/16)

typedef unsigned long long u64;

// device scratch: fp16 hi/lo fragment-packed weights (one 32-bit word = f16x2)
#define IPF_N (4 * IP_NT * IP_KC * 128)   // 294912 words
#define OPF_N (4 * OP_NT * OP_KC * 128)   // 131072 words
#define FIF_N (16 * FI_KC * 128)          // 12288 words
__device__ unsigned g_ipf[IPF_N];
__device__ unsigned g_opf[OPF_N];
__device__ unsigned g_fif[FIF_N];
__device__ float g_A[(size_t)MAXB * 2 * DM];

// shared memory layout (floats)
#define OFF_APK   0                          // 4096: s_buf (stage0) / in_proj A-pack
#define OFF_HST   4096                       // 128*36 = 4608
#define OFF_ZX    (OFF_HST + DM*TST)         // 32*584 = 18688
#define OFF_DT    (OFF_ZX + LSEQ*ESTR)       // 256
#define OFF_DA    (OFF_DT + LSEQ*NH)         // 256
#define OFF_INV   (OFF_DA + LSEQ*NH)         // 32
#define OFF_INV2  (OFF_INV + LSEQ)           // 32
#define OFF_RED   (OFF_INV2 + LSEQ)          // 256
#define SMEM_FLOATS (OFF_RED + NT)           // 28224 floats = 112896 B

// packed A words in dead z-columns of s_zx: word w -> row w>>8, col w&255
#define ZIDX(w) ((((w) >> 8) * ESTR) + ((w) & 255))

__device__ __forceinline__ float sigmoidf_(float v) {
    return 1.f / (1.f + __expf(-v));
}
__device__ __forceinline__ u64 pk2(float lo, float hi) {
    u64 r; asm("mov.b64 %0,{%1,%2};" : "=l"(r) : "f"(lo), "f"(hi)); return r;
}
__device__ __forceinline__ u64 dup2(float v) { return pk2(v, v); }
__device__ __forceinline__ void upk2(u64 a, float& lo, float& hi) {
    asm("mov.b64 {%0,%1},%2;" : "=f"(lo), "=f"(hi) : "l"(a));
}
__device__ __forceinline__ u64 fma2_(u64 a, u64 b, u64 c) {
    u64 d; asm("fma.rn.f32x2 %0,%1,%2,%3;" : "=l"(d) : "l"(a), "l"(b), "l"(c)); return d;
}
__device__ __forceinline__ u64 mul2_(u64 a, u64 b) {
    u64 d; asm("mul.rn.f32x2 %0,%1,%2;" : "=l"(d) : "l"(a), "l"(b)); return d;
}

// convert (v0, v1) -> packed f16x2 (v0 in low half, matching MMA fragment order)
__device__ __forceinline__ unsigned hcvt(float v0, float v1) {
    unsigned r;
    asm("cvt.rn.f16x2.f32 %0,%1,%2;" : "=r"(r) : "f"(v1), "f"(v0));
    return r;
}
// split (v0, v1) -> fp16 hi (rn) and lo (rn of residual)
__device__ __forceinline__ void hsplit(float v0, float v1, unsigned& hi, unsigned& lo) {
    hi = hcvt(v0, v1);
    __half2 h = *reinterpret_cast<__half2*>(&hi);
    float h0 = __low2float(h), h1 = __high2float(h);
    lo = hcvt(v0 - h0, v1 - h1);
}
__device__ __forceinline__ void mma_f16(float* d, const unsigned* a,
                                        unsigned b0, unsigned b1) {
    asm volatile(
        "mma.sync.aligned.m16n8k16.row.col.f32.f16.f16.f32 "
        "{%0,%1,%2,%3},{%4,%5,%6,%7},{%8,%9},{%0,%1,%2,%3};"
        : "+f"(d[0]), "+f"(d[1]), "+f"(d[2]), "+f"(d[3])
        : "r"(a[0]), "r"(a[1]), "r"(a[2]), "r"(a[3]), "r"(b0), "r"(b1));
}

// ---- prep: fold norms, fp16 hi/lo split, B-fragment lane order --------------
__global__ void prep_weights(const float* __restrict__ ipw,
                             const float* __restrict__ bnw,
                             const float* __restrict__ opw,
                             const float* __restrict__ mnw,
                             const float* __restrict__ fiw) {
    int i = blockIdx.x * blockDim.x + threadIdx.x;
    if (i < IPF_N) {
        int blk = i / (IP_NT * IP_KC * 128);
        int r   = i - blk * (IP_NT * IP_KC * 128);
        int n   = r / (IP_KC * 128);
        int q   = r - n * (IP_KC * 128);
        int kc  = q >> 7;
        int rem = q & 127;
        int lane = rem >> 2, comp = rem & 3;
        int g = lane >> 2, c = lane & 3;
        int e  = n * 8 + g;
        int k0 = kc * 16 + 2 * c + ((comp & 1) ? 8 : 0);
        float v0 = 0.f, v1 = 0.f;
        if (e < EPROJ) {
            v0 = ipw[((size_t)blk * EPROJ + e) * DM + k0]     * bnw[blk * DM + k0];
            v1 = ipw[((size_t)blk * EPROJ + e) * DM + k0 + 1] * bnw[blk * DM + k0 + 1];
        }
        unsigned hi, lo;
        hsplit(v0, v1, hi, lo);
        g_ipf[i] = (comp < 2) ? hi : lo;
    } else if (i < IPF_N + OPF_N) {
        int j   = i - IPF_N;
        int blk = j >> 15;
        int r   = j & 32767;
        int n   = r >> 11;
        int q   = r & 2047;
        int kc  = q >> 7;
        int rem = q & 127;
        int lane = rem >> 2, comp = rem & 3;
        int g = lane >> 2, c = lane & 3;
        int d  = n * 8 + g;
        int e0 = kc * 16 + 2 * c + ((comp & 1) ? 8 : 0);
        float v0 = opw[((size_t)blk * DM + d) * DIN + e0]     * mnw[blk * DIN + e0];
        float v1 = opw[((size_t)blk * DM + d) * DIN + e0 + 1] * mnw[blk * DIN + e0 + 1];
        unsigned hi, lo;
        hsplit(v0, v1, hi, lo);
        g_opf[j] = (comp < 2) ? hi : lo;
    } else if (i < IPF_N + OPF_N + FIF_N) {
        int j   = i - IPF_N - OPF_N;
        int n   = j / (FI_KC * 128);
        int q   = j - n * (FI_KC * 128);
        int kc  = q >> 7;
        int rem = q & 127;
        int lane = rem >> 2, comp = rem & 3;
        int g = lane >> 2, c = lane & 3;
        int d  = n * 8 + g;
        int k0 = kc * 16 + 2 * c + ((comp & 1) ? 8 : 0);
        float v0 = fiw[d * CIN + k0];
        float v1 = fiw[d * CIN + k0 + 1];
        unsigned hi, lo;
        hsplit(v0, v1, hi, lo);
        g_fif[j] = (comp < 2) ? hi : lo;
    }
}

// ---- finalize ----------------------------------------------------------------
__global__ void finalize_kernel(const float* __restrict__ fow,
                                const float* __restrict__ fob,
                                const float* __restrict__ olw,
                                const float* __restrict__ olb,
                                float* __restrict__ out, int B) {
    int idx = blockIdx.x * blockDim.x + threadIdx.x;
    if (idx >= B * COUT) return;
    int b = idx / COUT, o = idx - b * COUT;
    float Swl = 0.f;
#pragma unroll
    for (int t = 0; t < LSEQ; t++) Swl += olw[t];
    const float* A0 = g_A + (size_t)b * 2 * DM;
    float acc = 0.f;
#pragma unroll 4
    for (int d = 0; d < DM; d++) acc = fmaf(fow[o * DM + d], A0[d] + A0[DM + d], acc);
    out[idx] = acc + fob[o] * Swl + olb[0];
}

// ---- main: one CTA per (batch, direction) -------------------------------------
__global__ void __launch_bounds__(NT, 2) mamba_actor_kernel(
    const float* __restrict__ x,        // (B, 96)
    const float* __restrict__ buffer,   // (B, 96, 32)
    const float* __restrict__ fib,      // (128,)
    const float* __restrict__ cw,       // (4, 288, 4)
    const float* __restrict__ cb,       // (4, 288)
    const float* __restrict__ dtb,      // (4, 8)
    const float* __restrict__ alog,     // (4, 8)
    const float* __restrict__ Dp,       // (4, 8)
    const float* __restrict__ nfw,      // (2, 128)
    const float* __restrict__ olw,      // (1, 32)
    float* __restrict__ out)
{
    extern __shared__ float sm[];
    float*    s_buf  = sm + OFF_APK;   // stage0/fc_in only
    unsigned* s_apk  = reinterpret_cast<unsigned*>(sm + OFF_APK);
    float*    s_hsT  = sm + OFF_HST;   // [k][t], stride TST
    float*    s_zx   = sm + OFF_ZX;    // [t][e], stride ESTR
    unsigned* s_zxw  = reinterpret_cast<unsigned*>(sm + OFF_ZX);
    float*    s_dt   = sm + OFF_DT;
    float*    s_dA   = sm + OFF_DA;
    float*    s_inv  = sm + OFF_INV;
    float*    s_inv2 = sm + OFF_INV2;
    float*    s_red  = sm + OFF_RED;

    const int B    = gridDim.x >> 1;
    const int b    = blockIdx.x >> 1;
    const int dir  = blockIdx.x & 1;
    const int tid  = threadIdx.x;
    const int lane = tid & 31;
    const int warp = tid >> 5;
    const int kb   = lane & 3;      // c: thread-in-group
    const int tb   = lane >> 2;     // g: group id (row)

    // ---- Stage 0: shifted buffer -> smem (dir-flipped, [c][t]) + buf output --
    {
        const float* bsrc = buffer + (size_t)b * CIN * LSEQ;
        const float* xsrc = x + (size_t)b * CIN;
        float* bdst = out + (size_t)B * COUT + (size_t)b * CIN * LSEQ;
        for (int idx = tid; idx < CIN * LSEQ; idx += NT) {
            int c = idx >> 5, l = idx & 31;
            float v = (l < LSEQ - 1) ? bsrc[c * LSEQ + l + 1] : xsrc[c];
            int ls = dir ? (LSEQ - 1 - l) : l;
            s_buf[c * LSEQ + ls] = v;
            if (dir == 0) bdst[idx] = v;
        }
    }
    __syncthreads();

    // ---- fc_in A pack: buf fragments -> fp16 into s_zxw (free scratch) -------
    {
#pragma unroll
        for (int kk = 0; kk < 2; kk++) {
            int km = (kk == 0) ? warp : (8 + warp);
            if (kk == 0 || warp < 4) {
                int kc = km >> 1, m = km & 1;
#pragma unroll
                for (int r = 0; r < 4; r++) {
                    int tt = m * 16 + tb + (r & 1) * 8;
                    int k  = kc * 16 + 2 * kb + (r >> 1) * 8;
                    float v0 = s_buf[k * LSEQ + tt];
                    float v1 = s_buf[(k + 1) * LSEQ + tt];
                    s_zxw[km * 128 + lane * 4 + r] = hcvt(v0, v1);
                }
            }
        }
    }
    __syncthreads();

    // ---- fc_in via fp16 tensor cores (2-pass) + fused in_proj A-pack ---------
    {
        float dacc[2][2][4];
#pragma unroll
        for (int j = 0; j < 2; j++)
#pragma unroll
            for (int m = 0; m < 2; m++)
#pragma unroll
                for (int q = 0; q < 4; q++) dacc[j][m][q] = 0.f;
#pragma unroll
        for (int kc = 0; kc < FI_KC; kc++) {
            uint4 ah[2];
#pragma unroll
            for (int m = 0; m < 2; m++)
                ah[m] = *reinterpret_cast<const uint4*>(s_zxw + (kc * 2 + m) * 128 + lane * 4);
            uint4 bf0 = *reinterpret_cast<const uint4*>(
                g_fif + ((size_t)((warp * 2 + 0) * FI_KC + kc)) * 128 + lane * 4);
            uint4 bf1 = *reinterpret_cast<const uint4*>(
                g_fif + ((size_t)((warp * 2 + 1) * FI_KC + kc)) * 128 + lane * 4);
            mma_f16(dacc[0][0], &ah[0].x, bf0.x, bf0.y);
            mma_f16(dacc[0][1], &ah[1].x, bf0.x, bf0.y);
            mma_f16(dacc[1][0], &ah[0].x, bf1.x, bf1.y);
            mma_f16(dacc[1][1], &ah[1].x, bf1.x, bf1.y);
            mma_f16(dacc[0][0], &ah[0].x, bf0.z, bf0.w);
            mma_f16(dacc[0][1], &ah[1].x, bf0.z, bf0.w);
            mma_f16(dacc[1][0], &ah[0].x, bf1.z, bf1.w);
            mma_f16(dacc[1][1], &ah[1].x, bf1.z, bf1.w);
        }
#pragma unroll
        for (int j = 0; j < 2; j++) {
            int n  = warp * 2 + j;
            int d0 = n * 8 + 2 * kb;
            float f0 = fib[d0], f1 = fib[d0 + 1];
            unsigned wb = (((n >> 1) * 2) * 128) + lane * 4 + 2 * (n & 1);
#pragma unroll
            for (int m = 0; m < 2; m++) {
                int t0 = m * 16 + tb;
                float v0 = dacc[j][m][0] + f0;
                float v1 = dacc[j][m][1] + f1;
                float v2 = dacc[j][m][2] + f0;
                float v3 = dacc[j][m][3] + f1;
                s_hsT[d0 * TST + t0]           = v0;
                s_hsT[(d0 + 1) * TST + t0]     = v1;
                s_hsT[d0 * TST + t0 + 8]       = v2;
                s_hsT[(d0 + 1) * TST + t0 + 8] = v3;
                s_apk[wb + m * 128 + 0] = hcvt(v0, v1);
                s_apk[wb + m * 128 + 1] = hcvt(v2, v3);
            }
        }
    }
    __syncthreads();

    for (int l = 0; l < 2; l++) {
        const int blk = dir * 2 + l;

        // ---- block rmsnorm partials (pack already fused into epilogues) ------
        {
            float s = 0.f;
#pragma unroll
            for (int q = 0; q < 16; q++) {
                float v = s_hsT[(warp * 16 + q) * TST + lane];
                s += v * v;
            }
            s_red[warp * 32 + lane] = s;
        }
        __syncthreads();
        if (tid < 32) {
            float s = 0.f;
#pragma unroll
            for (int w = 0; w < 8; w++) s += s_red[w * 32 + tid];
            s_inv[tid] = rsqrtf(s * (1.f / DM) + EPS);
        }
        __syncthreads();

        // ---- in_proj via fp16 tensor cores (2-pass, packed A, 72 tiles) -------
        {
            const unsigned* Wf = g_ipf + (size_t)blk * (IP_NT * IP_KC * 128);
            float dacc[9][2][4];
#pragma unroll
            for (int j = 0; j < 9; j++)
#pragma unroll
                for (int m = 0; m < 2; m++)
#pragma unroll
                    for (int q = 0; q < 4; q++) dacc[j][m][q] = 0.f;

#pragma unroll 1
            for (int kc = 0; kc < IP_KC; kc++) {
                uint4 ah[2];
#pragma unroll
                for (int m = 0; m < 2; m++) {
                    int km = kc * 2 + m;
                    ah[m] = *reinterpret_cast<const uint4*>(s_apk + km * 128 + lane * 4);
                }
#pragma unroll
                for (int jg = 0; jg < 3; jg++) {
                    uint4 bf[3];
#pragma unroll
                    for (int u = 0; u < 3; u++) {
                        int n = warp + (jg * 3 + u) * 8;
                        bf[u] = *reinterpret_cast<const uint4*>(
                            Wf + ((size_t)(n * IP_KC + kc)) * 128 + lane * 4);
                    }
#pragma unroll
                    for (int u = 0; u < 3; u++) {
                        int j = jg * 3 + u;
                        mma_f16(dacc[j][0], &ah[0].x, bf[u].x, bf[u].y);
                        mma_f16(dacc[j][1], &ah[1].x, bf[u].x, bf[u].y);
                    }
#pragma unroll
                    for (int u = 0; u < 3; u++) {
                        int j = jg * 3 + u;
                        mma_f16(dacc[j][0], &ah[0].x, bf[u].z, bf[u].w);
                        mma_f16(dacc[j][1], &ah[1].x, bf[u].z, bf[u].w);
                    }
                }
            }
            // epilogue: scale rows by inv[t], store to zx
#pragma unroll
            for (int j = 0; j < 9; j++) {
                int n = warp + j * 8;
#pragma unroll
                for (int m = 0; m < 2; m++) {
                    int t0 = m * 16 + tb;
                    float i0 = s_inv[t0], i1 = s_inv[t0 + 8];
                    int e0 = n * 8 + 2 * kb;
                    float2 v0 = make_float2(dacc[j][m][0] * i0, dacc[j][m][1] * i0);
                    float2 v1 = make_float2(dacc[j][m][2] * i1, dacc[j][m][3] * i1);
                    *reinterpret_cast<float2*>(s_zx + t0 * ESTR + e0) = v0;
                    *reinterpret_cast<float2*>(s_zx + (t0 + 8) * ESTR + e0) = v1;
                }
            }
        }
        __syncthreads();

        // ---- dt/dA (256 threads == 32 t * 8 heads) + conv boundary pre-reads --
        {
            int t = tid >> 3, h = tid & 7;
            float v  = s_zx[t * ESTR + DIN + CDIM + h] + dtb[blk * NH + h];
            float sp = (v > 20.f) ? v : log1pf(__expf(v));
            s_dt[t * NH + h] = sp;
            s_dA[t * NH + h] = __expf(-__expf(alog[blk * NH + h]) * sp);
        }
        float pre[5][3];
        {
            int k = 0;
            for (int u = tid; u < 4 * CDIM; u += NT, k++) {
                int seg = u / CDIM;
                int c   = u - seg * CDIM;
                if (seg) {
                    const float* col = s_zx + DIN + c;
                    int t0 = seg * 8;
                    pre[k][0] = col[(t0 - 3) * ESTR];
                    pre[k][1] = col[(t0 - 2) * ESTR];
                    pre[k][2] = col[(t0 - 1) * ESTR];
                }
            }
        }
        __syncthreads();

        // ---- causal depthwise conv (k=4) + silu, (c, t-quarter) units ----------
        {
            int k = 0;
            for (int u = tid; u < 4 * CDIM; u += NT, k++) {
                int seg = u / CDIM;
                int c   = u - seg * CDIM;
                float4 w4 = *reinterpret_cast<const float4*>(cw + ((size_t)blk * CDIM + c) * 4);
                float bb  = cb[blk * CDIM + c];
                float x0, x1, x2;
                if (seg) { x0 = pre[k][0]; x1 = pre[k][1]; x2 = pre[k][2]; }
                else     { x0 = 0.f; x1 = 0.f; x2 = 0.f; }
                float* col = s_zx + DIN + c + seg * 8 * ESTR;
#pragma unroll
                for (int tt = 0; tt < 8; tt++) {
                    float xc = col[tt * ESTR];
                    float o  = fmaf(w4.x, x0, fmaf(w4.y, x1, fmaf(w4.z, x2, fmaf(w4.w, xc, bb))));
                    col[tt * ESTR] = o * sigmoidf_(o);
                    x0 = x1; x1 = x2; x2 = xc;
                }
            }
        }
        __syncthreads();

        // ---- SSM scan (+ fused gate): thread = (head, p) ----------------------
        {
            int h = tid >> 5;
            u64 st2[NH];
#pragma unroll
            for (int n = 0; n < 8; n++) st2[n] = 0ull;
            float dskip = Dp[blk * NH + h];
            for (int t = 0; t < LSEQ; t++) {
                float* row = s_zx + t * ESTR;
                float dAv = s_dA[t * NH + h];
                float dtv = s_dt[t * NH + h];
                float xv  = row[DIN + tid];
                u64 dA2  = dup2(dAv);
                u64 dtx2 = dup2(dtv * xv);
                const ulonglong2* Bp = reinterpret_cast<const ulonglong2*>(row + 2 * DIN);
                const ulonglong2* Cp = reinterpret_cast<const ulonglong2*>(row + 2 * DIN + DST);
                u64 y2 = 0ull;
#pragma unroll
                for (int q = 0; q < 4; q++) {
                    ulonglong2 b2 = Bp[q];
                    ulonglong2 c2 = Cp[q];
                    st2[2*q]   = fma2_(st2[2*q],   dA2, mul2_(dtx2, b2.x));
                    y2         = fma2_(st2[2*q],   c2.x, y2);
                    st2[2*q+1] = fma2_(st2[2*q+1], dA2, mul2_(dtx2, b2.y));
                    y2         = fma2_(st2[2*q+1], c2.y, y2);
                }
                float ylo, yhi;
                upk2(y2, ylo, yhi);
                float yv = fmaf(dskip, xv, ylo + yhi);
                float z  = row[tid];
                row[DIN + tid] = yv * z * sigmoidf_(z);   // fused gate
            }
        }
        __syncthreads();

        // ---- mixer rmsnorm partials + out_proj A pack (fp16 hi, z cols dead) ---
        {
            int t = tid >> 3, part = tid & 7;
            const float4* gp = reinterpret_cast<const float4*>(s_zx + t * ESTR + DIN + part * 32);
            float s = 0.f;
#pragma unroll
            for (int q = 0; q < 8; q++) {
                float4 v = gp[q];
                s += v.x * v.x + v.y * v.y + v.z * v.z + v.w * v.w;
            }
            s += __shfl_xor_sync(0xffffffffu, s, 1);
            s += __shfl_xor_sync(0xffffffffu, s, 2);
            s += __shfl_xor_sync(0xffffffffu, s, 4);
            if (part == 0) s_inv2[t] = rsqrtf(s * (1.f / DIN) + EPS);
        }
        {
#pragma unroll
            for (int kk = 0; kk < 4; kk++) {
                int km = warp + kk * 8;         // 0..31 = kc*2 + m
                int kc = km >> 1, m = km & 1;
#pragma unroll
                for (int r = 0; r < 4; r++) {
                    int tt = m * 16 + tb + (r & 1) * 8;
                    int e  = DIN + kc * 16 + 2 * kb + (r >> 1) * 8;
                    float2 v = *reinterpret_cast<const float2*>(s_zx + tt * ESTR + e);
                    int w = km * 128 + lane * 4 + r;
                    s_zxw[ZIDX(w)] = hcvt(v.x, v.y);
                }
            }
        }
        __syncthreads();

        // ---- out_proj (2-pass, packed A) + residual + fused next-layer A-pack --
        {
            const unsigned* Wf = g_opf + (size_t)blk * (OP_NT * OP_KC * 128);
            float dacc[2][2][4];
#pragma unroll
            for (int j = 0; j < 2; j++)
#pragma unroll
                for (int m = 0; m < 2; m++)
#pragma unroll
                    for (int q = 0; q < 4; q++) dacc[j][m][q] = 0.f;

#pragma unroll 1
            for (int kc = 0; kc < OP_KC; kc++) {
                uint4 ah[2];
#pragma unroll
                for (int m = 0; m < 2; m++) {
                    int w0 = (kc * 2 + m) * 128 + lane * 4;
                    ah[m] = *reinterpret_cast<const uint4*>(s_zxw + ZIDX(w0));
                }
                uint4 bf0 = *reinterpret_cast<const uint4*>(
                    Wf + ((size_t)((warp + 0) * OP_KC + kc)) * 128 + lane * 4);
                uint4 bf1 = *reinterpret_cast<const uint4*>(
                    Wf + ((size_t)((warp + 8) * OP_KC + kc)) * 128 + lane * 4);
                mma_f16(dacc[0][0], &ah[0].x, bf0.x, bf0.y);
                mma_f16(dacc[0][1], &ah[1].x, bf0.x, bf0.y);
                mma_f16(dacc[1][0], &ah[0].x, bf1.x, bf1.y);
                mma_f16(dacc[1][1], &ah[1].x, bf1.x, bf1.y);
                mma_f16(dacc[0][0], &ah[0].x, bf0.z, bf0.w);
                mma_f16(dacc[0][1], &ah[1].x, bf0.z, bf0.w);
                mma_f16(dacc[1][0], &ah[0].x, bf1.z, bf1.w);
                mma_f16(dacc[1][1], &ah[1].x, bf1.z, bf1.w);
            }
            // epilogue: hsT[d][t] += inv2[t] * D[t][d]; emit next-layer A-frags
#pragma unroll
            for (int j = 0; j < 2; j++) {
                int n  = warp + j * 8;
                int d0 = n * 8 + 2 * kb;
                unsigned wb = (((n >> 1) * 2) * 128) + lane * 4 + 2 * (n & 1);
#pragma unroll
                for (int m = 0; m < 2; m++) {
                    int t0 = m * 16 + tb;
                    float i0 = s_inv2[t0], i1 = s_inv2[t0 + 8];
                    float v0 = s_hsT[d0 * TST + t0]           + dacc[j][m][0] * i0;
                    float v1 = s_hsT[(d0 + 1) * TST + t0]     + dacc[j][m][1] * i0;
                    float v2 = s_hsT[d0 * TST + t0 + 8]       + dacc[j][m][2] * i1;
                    float v3 = s_hsT[(d0 + 1) * TST + t0 + 8] + dacc[j][m][3] * i1;
                    s_hsT[d0 * TST + t0]           = v0;
                    s_hsT[(d0 + 1) * TST + t0]     = v1;
                    s_hsT[d0 * TST + t0 + 8]       = v2;
                    s_hsT[(d0 + 1) * TST + t0 + 8] = v3;
                    if (l == 0) {
                        s_apk[wb + m * 128 + 0] = hcvt(v0, v1);
                        s_apk[wb + m * 128 + 1] = hcvt(v2, v3);
                    }
                }
            }
        }
        __syncthreads();
    } // layer

    // ---- final rmsnorm(norm_f) over d ------------------------------------------
    {
        float s = 0.f;
#pragma unroll
        for (int q = 0; q < 16; q++) {
            float v = s_hsT[(warp * 16 + q) * TST + lane];
            s += v * v;
        }
        s_red[warp * 32 + lane] = s;
    }
    __syncthreads();
    if (tid < 32) {
        float s = 0.f;
#pragma unroll
        for (int w = 0; w < 8; w++) s += s_red[w * 32 + tid];
        s_inv[tid] = rsqrtf(s * (1.f / DM) + EPS);
    }
    __syncthreads();

    // ---- L-weighted accumulate -> g_A ------------------------------------------
    if (tid < DM) {
        const float* hrow = s_hsT + tid * TST;
        float s = 0.f;
#pragma unroll
        for (int t = 0; t < LSEQ; t++) {
            float wl = olw[dir ? (LSEQ - 1 - t) : t];
            s = fmaf(wl * s_inv[t], hrow[t], s);
        }
        g_A[((size_t)b * 2 + dir) * DM + tid] = s * nfw[dir * DM + tid];
    }
}

extern "C" void kernel_launch(void* const* d_in, const int* in_sizes, int n_in,
                              void* d_out, int out_size) {
    const float* x      = (const float*)d_in[0];
    const float* buffer = (const float*)d_in[1];
    const float* fiw    = (const float*)d_in[2];
    const float* fib    = (const float*)d_in[3];
    const float* bnw    = (const float*)d_in[4];
    const float* ipw    = (const float*)d_in[5];
    const float* cw     = (const float*)d_in[6];
    const float* cb     = (const float*)d_in[7];
    const float* dtb    = (const float*)d_in[8];
    const float* alog   = (const float*)d_in[9];
    const float* Dp     = (const float*)d_in[10];
    const float* mnw    = (const float*)d_in[11];
    const float* opw    = (const float*)d_in[12];
    const float* nfw    = (const float*)d_in[13];
    const float* fow    = (const float*)d_in[14];
    const float* fob    = (const float*)d_in[15];
    const float* olw    = (const float*)d_in[16];
    const float* olb    = (const float*)d_in[17];
    float* out = (float*)d_out;

    int B = in_sizes[0] / CIN;   // 1024
    size_t smem_bytes = (size_t)SMEM_FLOATS * sizeof(float);

    cudaFuncSetAttribute(mamba_actor_kernel,
                         cudaFuncAttributeMaxDynamicSharedMemorySize,
                         (int)smem_bytes);

    int prep_total = IPF_N + OPF_N + FIF_N;
    prep_weights<<<(prep_total + 255) / 256, 256>>>(ipw, bnw, opw, mnw, fiw);

    mamba_actor_kernel<<<2 * B, NT, smem_bytes>>>(
        x, buffer, fib, cw, cb, dtb, alog,
        Dp, nfw, olw, out);

    finalize_kernel<<<(B * COUT + 255) / 256, 256>>>(fow, fob, olw, olb, out, B);
}